// round 6
// baseline (speedup 1.0000x reference)
#include <cuda_runtime.h>
#include <cuda_bf16.h>
#include <math.h>

// ---------------- problem constants ----------------
// B=1, N=6, X=Y=25 (L=625), W1=W2=8 (Qn=384), w1=w2=4 (Kn=96), D=128, M=4 heads, dh=32

#define LTOT 625
#define QN   384
#define KN   96

// ---------------- device constants (converted once) ----------------
__device__ __nv_bfloat16 g_wq[16384];
__device__ __nv_bfloat16 g_wkw[16384];
__device__ __nv_bfloat16 g_wv[16384];
__device__ __nv_bfloat16 g_wp[16384];
__device__ float g_cos[QN * 32];
__device__ float g_sin[QN * 32];
__device__ float g_scales[4];

// ---------------- helpers ----------------
__device__ __forceinline__ unsigned pk(float a, float b) {
    __nv_bfloat162 h = __floats2bfloat162_rn(a, b);
    return *reinterpret_cast<unsigned*>(&h);
}
__device__ __forceinline__ unsigned ssa(const void* p) {
    return (unsigned)__cvta_generic_to_shared(p);
}
__device__ __forceinline__ void ldsm4(unsigned r[4], unsigned addr) {
    asm volatile("ldmatrix.sync.aligned.m8n8.x4.shared.b16 {%0,%1,%2,%3}, [%4];\n"
                 : "=r"(r[0]), "=r"(r[1]), "=r"(r[2]), "=r"(r[3]) : "r"(addr));
}
__device__ __forceinline__ void mma16816(float c[4], const unsigned a[4], const unsigned b[2]) {
    asm volatile(
        "mma.sync.aligned.m16n8k16.row.col.f32.bf16.bf16.f32 "
        "{%0,%1,%2,%3}, {%4,%5,%6,%7}, {%8,%9}, {%0,%1,%2,%3};\n"
        : "+f"(c[0]), "+f"(c[1]), "+f"(c[2]), "+f"(c[3])
        : "r"(a[0]), "r"(a[1]), "r"(a[2]), "r"(a[3]), "r"(b[0]), "r"(b[1]));
}
__device__ __forceinline__ void cpa16(void* dst, const void* src) {
    asm volatile("cp.async.cg.shared.global [%0], [%1], 16;\n"
                 :: "r"(ssa(dst)), "l"(src));
}
__device__ __forceinline__ void cpa_commit() {
    asm volatile("cp.async.commit_group;\n");
}
template<int N> __device__ __forceinline__ void cpa_wait() {
    asm volatile("cp.async.wait_group %0;\n" :: "n"(N));
}
__device__ __forceinline__ void barg(int id) {
    asm volatile("bar.sync %0, %1;\n" :: "r"(id), "r"(256) : "memory");
}

// ---------------- kernel 0: constants prep ----------------
__global__ __launch_bounds__(256) void prep_const_kernel(
    const float* __restrict__ wq, const float* __restrict__ wk,
    const float* __restrict__ wv, const float* __restrict__ wp,
    const float* __restrict__ freqs, const float* __restrict__ gate,
    const float* __restrict__ als)
{
    int idx = blockIdx.x * 256 + threadIdx.x;
    if (idx < 16384) {
        g_wq[idx] = __float2bfloat16(wq[idx]);
    } else if (idx < 32768) {
        g_wkw[idx - 16384] = __float2bfloat16(wk[idx - 16384]);
    } else if (idx < 49152) {
        g_wv[idx - 32768] = __float2bfloat16(wv[idx - 32768]);
    } else if (idx < 65536) {
        g_wp[idx - 49152] = __float2bfloat16(wp[idx - 49152]);
    } else if (idx < 65536 + QN * 32) {
        int j = idx - 65536;
        float f = freqs[j];            // (400,32) row-major, t<384 prefix
        g_cos[j] = cosf(f);
        g_sin[j] = sinf(f);
    } else if (idx < 65536 + QN * 32 + 4) {
        int m = idx - (65536 + QN * 32);
        float temp = als[m] - 0.5f * logf(32.0f);   // als + log(dh^-0.5)
        float ga = fminf(fmaxf(gate[m], 0.0f), 1.0f);
        g_scales[m] = temp * ga;
    }
}

// ---------------- fused kernel: one block per l-tile ----------------
// smem element offsets (bf16 elems):
//   sK   : 4 heads * 96 * 40            = 15360
//   sVt  : 4 heads * 32 * 104           = 13312
//   sW0  : 128 * 136                    = 17408
//   sW1  : 128 * 136                    = 17408
//   sX   : 64 * 136                     =  8704
//   sRaw : 2 groups * 2 bufs * 4096 f32 = 32768 f32 = 65536 elems
#define E_K   0
#define E_VT  15360
#define E_W0  28672
#define E_W1  46080
#define E_X   63488
#define E_RAW 72192
#define SMEM_ELEMS (72192 + 32768)
#define SMEM_BYTES (SMEM_ELEMS * 2)

__global__ __launch_bounds__(512, 1) void fused_kernel(
    const float* __restrict__ q, const float* __restrict__ k,
    const float* __restrict__ v, const float* __restrict__ skip,
    const float* __restrict__ lnqg, const float* __restrict__ lnqb,
    const float* __restrict__ lnkg, const float* __restrict__ lnkb,
    const float* __restrict__ lnvg, const float* __restrict__ lnvb,
    const float* __restrict__ bq, const float* __restrict__ bk,
    const float* __restrict__ bv, const float* __restrict__ bproj,
    float* __restrict__ out)
{
    extern __shared__ __nv_bfloat16 sm[];
    __nv_bfloat16* sK  = sm + E_K;
    __nv_bfloat16* sVt = sm + E_VT;
    __nv_bfloat16* sW0 = sm + E_W0;
    __nv_bfloat16* sW1 = sm + E_W1;
    __nv_bfloat16* sX  = sm + E_X;
    float* sRawAll = reinterpret_cast<float*>(sm + E_RAW);

    int l = blockIdx.x;
    int tid = threadIdx.x;
    int g = tid >> 8;              // thread group (0/1), 256 threads each
    int tl = tid & 255;
    int wid = tid >> 5, lane = tid & 31;
    int wg = wid & 7;              // warp index within group
    int gq = lane >> 2, t4 = lane & 3;
    int bid = 1 + g;               // named barrier id for this group

    int mrow = (wg & 1) * 16;      // row-half within 32-row chunk
    int mh = wg >> 1;              // head

    float* rb[2] = { sRawAll + g * 8192, sRawAll + g * 8192 + 4096 };

    __nv_bfloat16* sXg = sX + g * 32 * 136;
    unsigned abaseA = ssa(&sXg[(mrow + (lane & 15)) * 136 + ((lane >> 4) << 3)]);

    int lrow = tl >> 3, lsub = tl & 7;   // LN mapping: 8 threads/row

    // =========================== Phase A: K (group 0) / V (group 1) ===========================
    const float* xin  = g ? v : k;
    {
        // cp.async: own-group weight matrix
        const __nv_bfloat16* wsrc = g ? g_wv : g_wkw;
        __nv_bfloat16* wdst = g ? sW1 : sW0;
        #pragma unroll
        for (int i = tl; i < 2048; i += 256)
            cpa16(wdst + (i >> 4) * 136 + (i & 15) * 8, wsrc + i * 8);
        cpa_commit();
        // prefetch kv chunks 0, 1
        #pragma unroll
        for (int c = 0; c < 2; c++) {
            float* dst = rb[c];
            #pragma unroll
            for (int j = 0; j < 4; j++) {
                int i = tl + 256 * j;
                int row = i >> 5, col = i & 31;
                int t = c * 32 + row;
                int n = t >> 4, rem = t & 15;
                cpa16(dst + row * 128 + col * 4,
                      xin + ((size_t)(n * LTOT + l) * 16 + rem) * 128 + col * 4);
            }
            cpa_commit();
        }
    }

    {
        const float* lng  = g ? lnvg : lnkg;
        const float* lnb_ = g ? lnvb : lnkb;
        const float* bia  = g ? bv : bk;
        __nv_bfloat16* sWg = g ? sW1 : sW0;
        unsigned bbase0 = ssa(&sWg[(mh * 32 + ((lane >> 4) * 8) + (lane & 7)) * 136 + (((lane >> 3) & 1) << 3)]);
        unsigned bbase1 = bbase0 + 16 * 136 * 2;

        for (int c = 0; c < 3; c++) {
            if (c < 2) cpa_wait<1>(); else cpa_wait<0>();
            barg(bid);

            // LayerNorm 32 rows from smem raw (conflict-free stride-32 mapping)
            float vv[16];
            {
                const float* rp = rb[c & 1] + lrow * 128;
                #pragma unroll
                for (int i = 0; i < 4; i++) {
                    float4 f = *reinterpret_cast<const float4*>(rp + (lsub + 8 * i) * 4);
                    vv[4 * i] = f.x; vv[4 * i + 1] = f.y; vv[4 * i + 2] = f.z; vv[4 * i + 3] = f.w;
                }
                float s = 0.f;
                #pragma unroll
                for (int i = 0; i < 16; i++) s += vv[i];
                #pragma unroll
                for (int o = 1; o < 8; o <<= 1) s += __shfl_xor_sync(0xffffffffu, s, o);
                float mu = s * (1.0f / 128.0f);
                float q2 = 0.f;
                #pragma unroll
                for (int i = 0; i < 16; i++) { float d = vv[i] - mu; q2 += d * d; }
                #pragma unroll
                for (int o = 1; o < 8; o <<= 1) q2 += __shfl_xor_sync(0xffffffffu, q2, o);
                float rs = rsqrtf(q2 * (1.0f / 128.0f) + 1e-5f);
                unsigned* xw = reinterpret_cast<unsigned*>(sXg) + lrow * 68;
                #pragma unroll
                for (int i = 0; i < 4; i++) {
                    int c0 = lsub * 4 + i * 32;
                    float a0 = (vv[4 * i]     - mu) * rs * lng[c0]     + lnb_[c0];
                    float a1 = (vv[4 * i + 1] - mu) * rs * lng[c0 + 1] + lnb_[c0 + 1];
                    float a2 = (vv[4 * i + 2] - mu) * rs * lng[c0 + 2] + lnb_[c0 + 2];
                    float a3 = (vv[4 * i + 3] - mu) * rs * lng[c0 + 3] + lnb_[c0 + 3];
                    xw[2 * lsub + 16 * i]     = pk(a0, a1);
                    xw[2 * lsub + 16 * i + 1] = pk(a2, a3);
                }
            }
            barg(bid);

            // prefetch chunk c+2 into the buffer LN just released
            if (c == 0) {
                float* dst = rb[0];
                #pragma unroll
                for (int j = 0; j < 4; j++) {
                    int i = tl + 256 * j;
                    int row = i >> 5, col = i & 31;
                    int t = 2 * 32 + row;
                    int n = t >> 4, rem = t & 15;
                    cpa16(dst + row * 128 + col * 4,
                          xin + ((size_t)(n * LTOT + l) * 16 + rem) * 128 + col * 4);
                }
                cpa_commit();
            }

            float acc[4][4] = {};
            #pragma unroll
            for (int kk = 0; kk < 128; kk += 16) {
                unsigned a[4], b01[4], b23[4];
                ldsm4(a, abaseA + kk * 2);
                ldsm4(b01, bbase0 + kk * 2);
                ldsm4(b23, bbase1 + kk * 2);
                mma16816(acc[0], a, &b01[0]);
                mma16816(acc[1], a, &b01[2]);
                mma16816(acc[2], a, &b23[0]);
                mma16816(acc[3], a, &b23[2]);
            }

            if (g == 0) {
                // K: +bias -> RoPE -> sK[(mh*96+t)*40 + j]
                #pragma unroll
                for (int r = 0; r < 2; r++) {
                    int t = c * 32 + mrow + gq + 8 * r;
                    __nv_bfloat16* op = sK + (mh * 96 + t) * 40;
                    #pragma unroll
                    for (int ntl = 0; ntl < 2; ntl++) {
                        int jlo = ntl * 8 + 2 * t4;
                        int jhi = jlo + 16;
                        float2 blo = *reinterpret_cast<const float2*>(&bia[mh * 32 + jlo]);
                        float2 bhi = *reinterpret_cast<const float2*>(&bia[mh * 32 + jhi]);
                        float plo0 = acc[ntl][2 * r] + blo.x;
                        float plo1 = acc[ntl][2 * r + 1] + blo.y;
                        float phi0 = acc[ntl + 2][2 * r] + bhi.x;
                        float phi1 = acc[ntl + 2][2 * r + 1] + bhi.y;
                        float2 cl = *reinterpret_cast<const float2*>(&g_cos[t * 32 + jlo]);
                        float2 sl = *reinterpret_cast<const float2*>(&g_sin[t * 32 + jlo]);
                        float2 ch = *reinterpret_cast<const float2*>(&g_cos[t * 32 + jhi]);
                        float2 sh = *reinterpret_cast<const float2*>(&g_sin[t * 32 + jhi]);
                        float y0 = plo0 * cl.x - phi0 * sl.x;
                        float y1 = plo1 * cl.y - phi1 * sl.y;
                        float y2 = phi0 * ch.x + plo0 * sh.x;
                        float y3 = phi1 * ch.y + plo1 * sh.y;
                        *reinterpret_cast<unsigned*>(op + jlo) = pk(y0, y1);
                        *reinterpret_cast<unsigned*>(op + jhi) = pk(y2, y3);
                    }
                }
            } else {
                // V: +bias -> transpose into sVt[(mh*32+j)*104 + t]
                #pragma unroll
                for (int r = 0; r < 2; r++) {
                    int t = c * 32 + mrow + gq + 8 * r;
                    #pragma unroll
                    for (int ntl = 0; ntl < 2; ntl++) {
                        int jlo = ntl * 8 + 2 * t4;
                        int jhi = jlo + 16;
                        float2 blo = *reinterpret_cast<const float2*>(&bv[mh * 32 + jlo]);
                        float2 bhi = *reinterpret_cast<const float2*>(&bv[mh * 32 + jhi]);
                        sVt[(mh * 32 + jlo) * 104 + t]     = __float2bfloat16(acc[ntl][2 * r] + blo.x);
                        sVt[(mh * 32 + jlo + 1) * 104 + t] = __float2bfloat16(acc[ntl][2 * r + 1] + blo.y);
                        sVt[(mh * 32 + jhi) * 104 + t]     = __float2bfloat16(acc[ntl + 2][2 * r] + bhi.x);
                        sVt[(mh * 32 + jhi + 1) * 104 + t] = __float2bfloat16(acc[ntl + 2][2 * r + 1] + bhi.y);
                    }
                }
            }
            barg(bid);
        }
    }

    __syncthreads();   // sK/sVt complete; sW0 free for wq

    // ---- cp.async: wq -> sW0 (block-wide), prefetch q chunks for iters 0,1 ----
    {
        #pragma unroll
        for (int i = tid; i < 2048; i += 512)
            cpa16(sW0 + (i >> 4) * 136 + (i & 15) * 8, g_wq + i * 8);
        cpa_commit();
        #pragma unroll
        for (int it = 0; it < 2; it++) {
            int c = 2 * it + g;
            float* dst = rb[it & 1];
            #pragma unroll
            for (int j = 0; j < 4; j++) {
                int i = tl + 256 * j;
                int row = i >> 5, col = i & 31;
                int t = c * 32 + row;
                int n = t >> 6, rem = t & 63;
                cpa16(dst + row * 128 + col * 4,
                      q + ((size_t)(n * LTOT + l) * 64 + rem) * 128 + col * 4);
            }
            cpa_commit();
        }
    }

    // =========================== Phase B: Q prep + attention + mean-accumulate ===========================
    __nv_bfloat16* sKh = sK + mh * 96 * 40;
    __nv_bfloat16* sVh = sVt + mh * 32 * 104;
    unsigned kb[6], vb[2];
    #pragma unroll
    for (int p = 0; p < 6; p++)
        kb[p] = ssa(&sKh[((2 * p + (lane >> 4)) * 8 + (lane & 7)) * 40 + (((lane >> 3) & 1) << 3)]);
    #pragma unroll
    for (int p = 0; p < 2; p++)
        vb[p] = ssa(&sVh[((2 * p + (lane >> 4)) * 8 + (lane & 7)) * 104 + (((lane >> 3) & 1) << 3)]);
    unsigned qb0 = ssa(&sW0[(mh * 32 + ((lane >> 4) * 8) + (lane & 7)) * 136 + (((lane >> 3) & 1) << 3)]);
    unsigned qb1 = qb0 + 16 * 136 * 2;
    float sc = g_scales[mh];

    float moacc[4][4] = {};   // mean-over-views accumulator

    for (int it = 0; it < 6; it++) {
        int c = 2 * it + g;
        if (it < 5) cpa_wait<1>(); else cpa_wait<0>();
        if (it == 0) __syncthreads(); else barg(bid);

        // LayerNorm from smem raw
        float vv[16];
        {
            const float* rp = rb[it & 1] + lrow * 128;
            #pragma unroll
            for (int i = 0; i < 4; i++) {
                float4 f = *reinterpret_cast<const float4*>(rp + (lsub + 8 * i) * 4);
                vv[4 * i] = f.x; vv[4 * i + 1] = f.y; vv[4 * i + 2] = f.z; vv[4 * i + 3] = f.w;
            }
            float s = 0.f;
            #pragma unroll
            for (int i = 0; i < 16; i++) s += vv[i];
            #pragma unroll
            for (int o = 1; o < 8; o <<= 1) s += __shfl_xor_sync(0xffffffffu, s, o);
            float mu = s * (1.0f / 128.0f);
            float q2 = 0.f;
            #pragma unroll
            for (int i = 0; i < 16; i++) { float d = vv[i] - mu; q2 += d * d; }
            #pragma unroll
            for (int o = 1; o < 8; o <<= 1) q2 += __shfl_xor_sync(0xffffffffu, q2, o);
            float rs = rsqrtf(q2 * (1.0f / 128.0f) + 1e-5f);
            unsigned* xw = reinterpret_cast<unsigned*>(sXg) + lrow * 68;
            #pragma unroll
            for (int i = 0; i < 4; i++) {
                int c0 = lsub * 4 + i * 32;
                float a0 = (vv[4 * i]     - mu) * rs * lnqg[c0]     + lnqb[c0];
                float a1 = (vv[4 * i + 1] - mu) * rs * lnqg[c0 + 1] + lnqb[c0 + 1];
                float a2 = (vv[4 * i + 2] - mu) * rs * lnqg[c0 + 2] + lnqb[c0 + 2];
                float a3 = (vv[4 * i + 3] - mu) * rs * lnqg[c0 + 3] + lnqb[c0 + 3];
                xw[2 * lsub + 16 * i]     = pk(a0, a1);
                xw[2 * lsub + 16 * i + 1] = pk(a2, a3);
            }
        }
        barg(bid);

        // prefetch q chunk for iter it+2 into released buffer
        if (it < 4) {
            int c2 = 2 * (it + 2) + g;
            float* dst = rb[it & 1];
            #pragma unroll
            for (int j = 0; j < 4; j++) {
                int i = tl + 256 * j;
                int row = i >> 5, col = i & 31;
                int t = c2 * 32 + row;
                int n = t >> 6, rem = t & 63;
                cpa16(dst + row * 128 + col * 4,
                      q + ((size_t)(n * LTOT + l) * 64 + rem) * 128 + col * 4);
            }
            cpa_commit();
        }

        // q-projection GEMM (16 rows x 32 cols of head mh)
        float acc[4][4] = {};
        #pragma unroll
        for (int kk = 0; kk < 128; kk += 16) {
            unsigned a[4], b01[4], b23[4];
            ldsm4(a, abaseA + kk * 2);
            ldsm4(b01, qb0 + kk * 2);
            ldsm4(b23, qb1 + kk * 2);
            mma16816(acc[0], a, &b01[0]);
            mma16816(acc[1], a, &b01[2]);
            mma16816(acc[2], a, &b23[0]);
            mma16816(acc[3], a, &b23[2]);
        }

        // epilogue in registers: +bias -> RoPE -> *scale -> A fragments
        unsigned aq0[4], aq1[4];
        {
            float F[4][4];
            #pragma unroll
            for (int r = 0; r < 2; r++) {
                int t = c * 32 + mrow + gq + 8 * r;
                #pragma unroll
                for (int ntl = 0; ntl < 2; ntl++) {
                    int jlo = ntl * 8 + 2 * t4;
                    int jhi = jlo + 16;
                    float2 blo = *reinterpret_cast<const float2*>(&bq[mh * 32 + jlo]);
                    float2 bhi = *reinterpret_cast<const float2*>(&bq[mh * 32 + jhi]);
                    float plo0 = acc[ntl][2 * r] + blo.x;
                    float plo1 = acc[ntl][2 * r + 1] + blo.y;
                    float phi0 = acc[ntl + 2][2 * r] + bhi.x;
                    float phi1 = acc[ntl + 2][2 * r + 1] + bhi.y;
                    float2 cl = *reinterpret_cast<const float2*>(&g_cos[t * 32 + jlo]);
                    float2 sl = *reinterpret_cast<const float2*>(&g_sin[t * 32 + jlo]);
                    float2 ch = *reinterpret_cast<const float2*>(&g_cos[t * 32 + jhi]);
                    float2 sh = *reinterpret_cast<const float2*>(&g_sin[t * 32 + jhi]);
                    F[ntl][2 * r]         = (plo0 * cl.x - phi0 * sl.x) * sc;
                    F[ntl][2 * r + 1]     = (plo1 * cl.y - phi1 * sl.y) * sc;
                    F[ntl + 2][2 * r]     = (phi0 * ch.x + plo0 * sh.x) * sc;
                    F[ntl + 2][2 * r + 1] = (phi1 * ch.y + plo1 * sh.y) * sc;
                }
            }
            aq0[0] = pk(F[0][0], F[0][1]); aq0[1] = pk(F[0][2], F[0][3]);
            aq0[2] = pk(F[1][0], F[1][1]); aq0[3] = pk(F[1][2], F[1][3]);
            aq1[0] = pk(F[2][0], F[2][1]); aq1[1] = pk(F[2][2], F[2][3]);
            aq1[2] = pk(F[3][0], F[3][1]); aq1[3] = pk(F[3][2], F[3][3]);
        }

        // S = Q K^T over 96 keys
        float sacc[12][4] = {};
        #pragma unroll
        for (int p = 0; p < 6; p++) {
            unsigned b[4];
            ldsm4(b, kb[p]);
            mma16816(sacc[2 * p], aq0, &b[0]);
            mma16816(sacc[2 * p + 1], aq0, &b[2]);
        }
        #pragma unroll
        for (int p = 0; p < 6; p++) {
            unsigned b[4];
            ldsm4(b, kb[p] + 32);
            mma16816(sacc[2 * p], aq1, &b[0]);
            mma16816(sacc[2 * p + 1], aq1, &b[2]);
        }

        // softmax over 96
        float mx0 = -1e30f, mx1 = -1e30f;
        #pragma unroll
        for (int nt = 0; nt < 12; nt++) {
            mx0 = fmaxf(mx0, fmaxf(sacc[nt][0], sacc[nt][1]));
            mx1 = fmaxf(mx1, fmaxf(sacc[nt][2], sacc[nt][3]));
        }
        mx0 = fmaxf(mx0, __shfl_xor_sync(0xffffffffu, mx0, 1));
        mx0 = fmaxf(mx0, __shfl_xor_sync(0xffffffffu, mx0, 2));
        mx1 = fmaxf(mx1, __shfl_xor_sync(0xffffffffu, mx1, 1));
        mx1 = fmaxf(mx1, __shfl_xor_sync(0xffffffffu, mx1, 2));
        float sm0 = 0.f, sm1 = 0.f;
        #pragma unroll
        for (int nt = 0; nt < 12; nt++) {
            sacc[nt][0] = __expf(sacc[nt][0] - mx0);
            sacc[nt][1] = __expf(sacc[nt][1] - mx0);
            sacc[nt][2] = __expf(sacc[nt][2] - mx1);
            sacc[nt][3] = __expf(sacc[nt][3] - mx1);
            sm0 += sacc[nt][0] + sacc[nt][1];
            sm1 += sacc[nt][2] + sacc[nt][3];
        }
        sm0 += __shfl_xor_sync(0xffffffffu, sm0, 1);
        sm0 += __shfl_xor_sync(0xffffffffu, sm0, 2);
        sm1 += __shfl_xor_sync(0xffffffffu, sm1, 1);
        sm1 += __shfl_xor_sync(0xffffffffu, sm1, 2);
        float r0i = 1.0f / sm0, r1i = 1.0f / sm1;
        #pragma unroll
        for (int nt = 0; nt < 12; nt++) {
            sacc[nt][0] *= r0i; sacc[nt][1] *= r0i;
            sacc[nt][2] *= r1i; sacc[nt][3] *= r1i;
        }

        // O += P V
        #pragma unroll
        for (int c6 = 0; c6 < 6; c6++) {
            unsigned a[4];
            a[0] = pk(sacc[2 * c6][0], sacc[2 * c6][1]);
            a[1] = pk(sacc[2 * c6][2], sacc[2 * c6][3]);
            a[2] = pk(sacc[2 * c6 + 1][0], sacc[2 * c6 + 1][1]);
            a[3] = pk(sacc[2 * c6 + 1][2], sacc[2 * c6 + 1][3]);
            #pragma unroll
            for (int p = 0; p < 2; p++) {
                unsigned b[4];
                ldsm4(b, vb[p] + c6 * 32);
                mma16816(moacc[2 * p], a, &b[0]);
                mma16816(moacc[2 * p + 1], a, &b[2]);
            }
        }
        barg(bid);
    }

    // =========================== Phase C: mean -> proj -> +skip -> out ===========================
    __syncthreads();   // all reads of sW0 (wq) and sRaw done

    float* sSkipF = sRawAll;   // 64*128 floats
    {
        #pragma unroll
        for (int i = tid; i < 2048; i += 512)
            cpa16(sSkipF + i * 4, skip + (size_t)l * 8192 + i * 4);
        cpa_commit();
        #pragma unroll
        for (int i = tid; i < 2048; i += 512)
            cpa16(sW0 + (i >> 4) * 136 + (i & 15) * 8, g_wp + i * 8);
        cpa_commit();
    }
    // write mean tile into sX (64 rows x 136) while copies fly
    {
        int uv0 = g * 32 + mrow;
        #pragma unroll
        for (int nt = 0; nt < 4; nt++) {
            int col = mh * 32 + nt * 8 + 2 * t4;
            #pragma unroll
            for (int r = 0; r < 2; r++) {
                int uvr = uv0 + gq + 8 * r;
                *reinterpret_cast<unsigned*>(&sX[uvr * 136 + col]) =
                    pk(moacc[nt][2 * r] * (1.0f / 6.0f), moacc[nt][2 * r + 1] * (1.0f / 6.0f));
            }
        }
    }
    cpa_wait<0>();
    __syncthreads();

    // proj GEMM: 64 rows x 128 cols; warp = (rowtile wid&3, coltile wid>>2)
    {
        int mrow2 = (wid & 3) * 16, cw = (wid >> 2) * 32;
        unsigned abase2 = ssa(&sX[(mrow2 + (lane & 15)) * 136 + ((lane >> 4) << 3)]);
        unsigned pb0 = ssa(&sW0[(cw + ((lane >> 4) * 8) + (lane & 7)) * 136 + (((lane >> 3) & 1) << 3)]);
        unsigned pb1 = pb0 + 16 * 136 * 2;
        float pacc[4][4] = {};
        #pragma unroll
        for (int kk = 0; kk < 128; kk += 16) {
            unsigned a[4], b01[4], b23[4];
            ldsm4(a, abase2 + kk * 2);
            ldsm4(b01, pb0 + kk * 2);
            ldsm4(b23, pb1 + kk * 2);
            mma16816(pacc[0], a, &b01[0]);
            mma16816(pacc[1], a, &b01[2]);
            mma16816(pacc[2], a, &b23[0]);
            mma16816(pacc[3], a, &b23[2]);
        }
        #pragma unroll
        for (int nt = 0; nt < 4; nt++) {
            int col = cw + nt * 8 + 2 * t4;
            float2 bp = *reinterpret_cast<const float2*>(&bproj[col]);
            #pragma unroll
            for (int r = 0; r < 2; r++) {
                int rloc = mrow2 + gq + 8 * r;
                int rowg = l * 64 + rloc;
                float2 sk = *reinterpret_cast<const float2*>(sSkipF + rloc * 128 + col);
                float2 o2;
                o2.x = pacc[nt][2 * r] + bp.x + sk.x;
                o2.y = pacc[nt][2 * r + 1] + bp.y + sk.y;
                *reinterpret_cast<float2*>(out + (size_t)rowg * 128 + col) = o2;
            }
        }
    }
}

// ---------------- launch ----------------
extern "C" void kernel_launch(void* const* d_in, const int* in_sizes, int n_in,
                              void* d_out, int out_size) {
    const float* q     = (const float*)d_in[0];
    const float* k     = (const float*)d_in[1];
    const float* v     = (const float*)d_in[2];
    const float* skip  = (const float*)d_in[3];
    const float* freqs = (const float*)d_in[4];
    const float* gate  = (const float*)d_in[5];
    const float* lnqg  = (const float*)d_in[6];
    const float* lnqb  = (const float*)d_in[7];
    const float* lnkg  = (const float*)d_in[8];
    const float* lnkb  = (const float*)d_in[9];
    const float* lnvg  = (const float*)d_in[10];
    const float* lnvb  = (const float*)d_in[11];
    const float* wq    = (const float*)d_in[12];
    const float* bq    = (const float*)d_in[13];
    const float* wk    = (const float*)d_in[14];
    const float* bk    = (const float*)d_in[15];
    const float* wv    = (const float*)d_in[16];
    const float* bv    = (const float*)d_in[17];
    const float* wproj = (const float*)d_in[18];
    const float* bproj = (const float*)d_in[19];
    const float* als   = (const float*)d_in[20];
    float* out = (float*)d_out;

    static int smem_set = 0;
    if (!smem_set) {
        cudaFuncSetAttribute(fused_kernel, cudaFuncAttributeMaxDynamicSharedMemorySize, SMEM_BYTES);
        smem_set = 1;
    }

    prep_const_kernel<<<305, 256>>>(wq, wk, wv, wproj, freqs, gate, als);
    fused_kernel<<<LTOT, 512, SMEM_BYTES>>>(q, k, v, skip,
                                            lnqg, lnqb, lnkg, lnkb, lnvg, lnvb,
                                            bq, bk, bv, bproj, out);
}

// round 7
// speedup vs baseline: 1.1068x; 1.1068x over previous
#include <cuda_runtime.h>
#include <cuda_bf16.h>
#include <math.h>

// ---------------- problem constants ----------------
// B=1, N=6, X=Y=25 (L=625), W1=W2=8 (Qn=384), w1=w2=4 (Kn=96), D=128, M=4 heads, dh=32

#define LTOT 625
#define QN   384

// ---------------- device constants / scratch ----------------
__device__ __nv_bfloat16 g_wq[16384];
__device__ __nv_bfloat16 g_wk[16384];
__device__ __nv_bfloat16 g_wv[16384];
__device__ __nv_bfloat16 g_wp[16384];
__device__ __nv_bfloat16 g_tmp[(size_t)LTOT * 32 * 128];   // even-half O-mean spill
__device__ float g_cos[QN * 32];
__device__ float g_sin[QN * 32];
__device__ float g_scales[4];

// ---------------- helpers ----------------
__device__ __forceinline__ unsigned pk(float a, float b) {
    __nv_bfloat162 h = __floats2bfloat162_rn(a, b);
    return *reinterpret_cast<unsigned*>(&h);
}
__device__ __forceinline__ unsigned ssa(const void* p) {
    return (unsigned)__cvta_generic_to_shared(p);
}
__device__ __forceinline__ void ldsm4(unsigned r[4], unsigned addr) {
    asm volatile("ldmatrix.sync.aligned.m8n8.x4.shared.b16 {%0,%1,%2,%3}, [%4];\n"
                 : "=r"(r[0]), "=r"(r[1]), "=r"(r[2]), "=r"(r[3]) : "r"(addr));
}
__device__ __forceinline__ void mma16816(float c[4], const unsigned a[4], const unsigned b[2]) {
    asm volatile(
        "mma.sync.aligned.m16n8k16.row.col.f32.bf16.bf16.f32 "
        "{%0,%1,%2,%3}, {%4,%5,%6,%7}, {%8,%9}, {%0,%1,%2,%3};\n"
        : "+f"(c[0]), "+f"(c[1]), "+f"(c[2]), "+f"(c[3])
        : "r"(a[0]), "r"(a[1]), "r"(a[2]), "r"(a[3]), "r"(b[0]), "r"(b[1]));
}
__device__ __forceinline__ void cpa16(void* dst, const void* src) {
    asm volatile("cp.async.cg.shared.global [%0], [%1], 16;\n"
                 :: "r"(ssa(dst)), "l"(src));
}
__device__ __forceinline__ void cpa_commit() {
    asm volatile("cp.async.commit_group;\n");
}
template<int N> __device__ __forceinline__ void cpa_wait() {
    asm volatile("cp.async.wait_group %0;\n" :: "n"(N));
}

// ---------------- kernel 0: constants prep ----------------
__global__ __launch_bounds__(256) void prep_const_kernel(
    const float* __restrict__ wq, const float* __restrict__ wk,
    const float* __restrict__ wv, const float* __restrict__ wp,
    const float* __restrict__ freqs, const float* __restrict__ gate,
    const float* __restrict__ als)
{
    int idx = blockIdx.x * 256 + threadIdx.x;
    if (idx < 16384) {
        g_wq[idx] = __float2bfloat16(wq[idx]);
    } else if (idx < 32768) {
        g_wk[idx - 16384] = __float2bfloat16(wk[idx - 16384]);
    } else if (idx < 49152) {
        g_wv[idx - 32768] = __float2bfloat16(wv[idx - 32768]);
    } else if (idx < 65536) {
        g_wp[idx - 49152] = __float2bfloat16(wp[idx - 49152]);
    } else if (idx < 65536 + QN * 32) {
        int j = idx - 65536;
        float f = freqs[j];            // (400,32) row-major, t<384 prefix
        g_cos[j] = cosf(f);
        g_sin[j] = sinf(f);
    } else if (idx < 65536 + QN * 32 + 4) {
        int m = idx - (65536 + QN * 32);
        float temp = als[m] - 0.5f * logf(32.0f);   // als + log(dh^-0.5)
        float ga = fminf(fmaxf(gate[m], 0.0f), 1.0f);
        g_scales[m] = temp * ga;
    }
}

// ---------------- smem layout (bf16 element offsets) ----------------
// sK   : 4*96*40  = 15360   K[s][d] padded stride 40, per head
// sVt  : 4*32*104 = 13312   V^T[d][s] padded stride 104, per head
// sW   : 128*128  = 16384   weights, XOR-swizzled 16B units
// raw  : 8192 elems (16 KB) fp32 LN staging 32x128; Phase C: bf16 O 64x128 swizzled
// sX   : 32*136   = 4352    LN bf16 output staging
#define E_K   0
#define E_VT  15360
#define E_W   28672
#define E_RAW 45056
#define E_X   53248
#define SMEM_ELEMS 57600
#define SMEM_BYTES (SMEM_ELEMS * 2)   // 115200

__device__ __forceinline__ void stage_w(__nv_bfloat16* sW, const __nv_bfloat16* w, int tid) {
    #pragma unroll
    for (int u = tid; u < 2048; u += 256) {
        int row = u >> 4, cu = u & 15;
        cpa16(sW + row * 128 + ((cu ^ (row & 7)) << 3), w + u * 8);
    }
}
__device__ __forceinline__ void stage_chunk(float* raw, const float* x, int l,
                                            int t0, int sh, int msk, int tid) {
    #pragma unroll
    for (int j = 0; j < 4; j++) {
        int idx = tid + 256 * j;
        int row = idx >> 5, c4 = idx & 31;
        int t = t0 + row;
        int n = t >> sh, rem = t & msk;
        cpa16(raw + row * 128 + c4 * 4,
              x + ((size_t)(n * LTOT + l) * (msk + 1) + rem) * 128 + c4 * 4);
    }
}

// ---------------- fused kernel: one block per l-tile, 2 blocks/SM ----------------
__global__ __launch_bounds__(256, 2) void fused_kernel(
    const float* __restrict__ q, const float* __restrict__ k,
    const float* __restrict__ v, const float* __restrict__ skip,
    const float* __restrict__ lnqg, const float* __restrict__ lnqb,
    const float* __restrict__ lnkg, const float* __restrict__ lnkb,
    const float* __restrict__ lnvg, const float* __restrict__ lnvb,
    const float* __restrict__ bq, const float* __restrict__ bk,
    const float* __restrict__ bv, const float* __restrict__ bproj,
    float* __restrict__ out)
{
    extern __shared__ __nv_bfloat16 sm[];
    __nv_bfloat16* sK  = sm + E_K;
    __nv_bfloat16* sVt = sm + E_VT;
    __nv_bfloat16* sW  = sm + E_W;
    float* raw = reinterpret_cast<float*>(sm + E_RAW);
    __nv_bfloat16* rawO = sm + E_RAW;
    __nv_bfloat16* sX  = sm + E_X;

    int l = blockIdx.x;
    int tid = threadIdx.x;
    int wid = tid >> 5, lane = tid & 31, gq = lane >> 2, t4 = lane & 3;
    int mrow = (wid & 1) * 16;            // 16-row half within 32-row chunk
    int mh = wid >> 1;                    // head
    int lrow = tid >> 3, lsub = tid & 7;  // LN: 8 threads/row

    unsigned sWb = ssa(sW);
    unsigned abase = ssa(&sX[(mrow + (lane & 15)) * 136 + ((lane >> 4) << 3)]);

    // weight B-fragment lane constants (swizzled sW; 16B units, row stride 256 B)
    int o01 = mh * 32 + ((lane >> 4) << 3) + (lane & 7);
    unsigned wrow01 = sWb + o01 * 256;
    unsigned wrow23 = wrow01 + 4096;      // +16 output rows
    int wrx = o01 & 7;
    int wu0 = (lane >> 3) & 1;

    // attention fragment bases
    __nv_bfloat16* sKh = sK + mh * 96 * 40;
    __nv_bfloat16* sVh = sVt + mh * 32 * 104;
    unsigned kb[6], vb[2];
    #pragma unroll
    for (int p = 0; p < 6; p++)
        kb[p] = ssa(&sKh[((2 * p + (lane >> 4)) * 8 + (lane & 7)) * 40 + (((lane >> 3) & 1) << 3)]);
    #pragma unroll
    for (int p = 0; p < 2; p++)
        vb[p] = ssa(&sVh[((2 * p + (lane >> 4)) * 8 + (lane & 7)) * 104 + (((lane >> 3) & 1) << 3)]);
    float sc = g_scales[mh];

    // initial: wk + first k chunk
    stage_w(sW, g_wk, tid);
    cpa_commit();
    stage_chunk(raw, k, l, 0, 4, 15, tid);
    cpa_commit();

    // =========================== Phase A: K (i=0..2) then V (i=3..5) prep ===========================
    for (int i = 0; i < 6; i++) {
        int isV = (i >= 3);
        cpa_wait<0>();
        __syncthreads();                        // chunk i arrived; prev GEMM done with sX/sW
        if (i == 3) { stage_w(sW, g_wv, tid); cpa_commit(); }

        // LayerNorm 32 rows
        {
            const float* lng  = isV ? lnvg : lnkg;
            const float* lnb_ = isV ? lnvb : lnkb;
            const float* rp = raw + lrow * 128;
            float vv[16];
            #pragma unroll
            for (int i4 = 0; i4 < 4; i4++) {
                float4 f = *reinterpret_cast<const float4*>(rp + (lsub + 8 * i4) * 4);
                vv[4 * i4] = f.x; vv[4 * i4 + 1] = f.y; vv[4 * i4 + 2] = f.z; vv[4 * i4 + 3] = f.w;
            }
            float s = 0.f;
            #pragma unroll
            for (int i2 = 0; i2 < 16; i2++) s += vv[i2];
            #pragma unroll
            for (int o = 1; o < 8; o <<= 1) s += __shfl_xor_sync(0xffffffffu, s, o);
            float mu = s * (1.0f / 128.0f);
            float q2 = 0.f;
            #pragma unroll
            for (int i2 = 0; i2 < 16; i2++) { float d = vv[i2] - mu; q2 += d * d; }
            #pragma unroll
            for (int o = 1; o < 8; o <<= 1) q2 += __shfl_xor_sync(0xffffffffu, q2, o);
            float rs = rsqrtf(q2 * (1.0f / 128.0f) + 1e-5f);
            unsigned* xw = reinterpret_cast<unsigned*>(sX) + lrow * 68;
            #pragma unroll
            for (int i4 = 0; i4 < 4; i4++) {
                int c0 = lsub * 4 + i4 * 32;
                float a0 = (vv[4 * i4]     - mu) * rs * lng[c0]     + lnb_[c0];
                float a1 = (vv[4 * i4 + 1] - mu) * rs * lng[c0 + 1] + lnb_[c0 + 1];
                float a2 = (vv[4 * i4 + 2] - mu) * rs * lng[c0 + 2] + lnb_[c0 + 2];
                float a3 = (vv[4 * i4 + 3] - mu) * rs * lng[c0 + 3] + lnb_[c0 + 3];
                xw[2 * lsub + 16 * i4]     = pk(a0, a1);
                xw[2 * lsub + 16 * i4 + 1] = pk(a2, a3);
            }
        }
        __syncthreads();                        // raw free, sX ready
        if (i == 3) cpa_wait<0>();              // wv must be resident before GEMM
        // prefetch next chunk into raw
        if (i < 2)       stage_chunk(raw, k, l, (i + 1) * 32, 4, 15, tid);
        else if (i < 5)  stage_chunk(raw, v, l, (i - 2) * 32, 4, 15, tid);
        else             stage_chunk(raw, q, l, 0, 6, 63, tid);
        cpa_commit();

        // GEMM: 32 rows x 128 cols
        float acc[4][4] = {};
        #pragma unroll
        for (int kk = 0; kk < 128; kk += 16) {
            unsigned uoff = ((((kk >> 3) + wu0) ^ wrx) << 4);
            unsigned a[4], b01[4], b23[4];
            ldsm4(a, abase + kk * 2);
            ldsm4(b01, wrow01 + uoff);
            ldsm4(b23, wrow23 + uoff);
            mma16816(acc[0], a, &b01[0]);
            mma16816(acc[1], a, &b01[2]);
            mma16816(acc[2], a, &b23[0]);
            mma16816(acc[3], a, &b23[2]);
        }

        if (!isV) {
            // K: +bias -> RoPE -> sK
            #pragma unroll
            for (int r = 0; r < 2; r++) {
                int t = i * 32 + mrow + gq + 8 * r;
                __nv_bfloat16* op = sK + (mh * 96 + t) * 40;
                #pragma unroll
                for (int ntl = 0; ntl < 2; ntl++) {
                    int jlo = ntl * 8 + 2 * t4;
                    int jhi = jlo + 16;
                    float2 blo = *reinterpret_cast<const float2*>(&bk[mh * 32 + jlo]);
                    float2 bhi = *reinterpret_cast<const float2*>(&bk[mh * 32 + jhi]);
                    float plo0 = acc[ntl][2 * r] + blo.x;
                    float plo1 = acc[ntl][2 * r + 1] + blo.y;
                    float phi0 = acc[ntl + 2][2 * r] + bhi.x;
                    float phi1 = acc[ntl + 2][2 * r + 1] + bhi.y;
                    float2 cl = *reinterpret_cast<const float2*>(&g_cos[t * 32 + jlo]);
                    float2 sl = *reinterpret_cast<const float2*>(&g_sin[t * 32 + jlo]);
                    float2 ch = *reinterpret_cast<const float2*>(&g_cos[t * 32 + jhi]);
                    float2 sh = *reinterpret_cast<const float2*>(&g_sin[t * 32 + jhi]);
                    *reinterpret_cast<unsigned*>(op + jlo) =
                        pk(plo0 * cl.x - phi0 * sl.x, plo1 * cl.y - phi1 * sl.y);
                    *reinterpret_cast<unsigned*>(op + jhi) =
                        pk(phi0 * ch.x + plo0 * sh.x, phi1 * ch.y + plo1 * sh.y);
                }
            }
        } else {
            // V: +bias -> transpose into sVt
            #pragma unroll
            for (int r = 0; r < 2; r++) {
                int t = (i - 3) * 32 + mrow + gq + 8 * r;
                #pragma unroll
                for (int ntl = 0; ntl < 2; ntl++) {
                    int jlo = ntl * 8 + 2 * t4;
                    int jhi = jlo + 16;
                    float2 blo = *reinterpret_cast<const float2*>(&bv[mh * 32 + jlo]);
                    float2 bhi = *reinterpret_cast<const float2*>(&bv[mh * 32 + jhi]);
                    sVt[(mh * 32 + jlo) * 104 + t]     = __float2bfloat16(acc[ntl][2 * r] + blo.x);
                    sVt[(mh * 32 + jlo + 1) * 104 + t] = __float2bfloat16(acc[ntl][2 * r + 1] + blo.y);
                    sVt[(mh * 32 + jhi) * 104 + t]     = __float2bfloat16(acc[ntl + 2][2 * r] + bhi.x);
                    sVt[(mh * 32 + jhi + 1) * 104 + t] = __float2bfloat16(acc[ntl + 2][2 * r + 1] + bhi.y);
                }
            }
        }
    }

    // =========================== Phase B: Q prep + attention + mean ===========================
    float moacc[4][4] = {};

    for (int j = 0; j < 12; j++) {
        int qc = (j < 6) ? 2 * j : 2 * j - 11;   // even uv-half first, then odd
        cpa_wait<0>();
        __syncthreads();
        if (j == 0) { stage_w(sW, g_wq, tid); cpa_commit(); }

        // LayerNorm (q)
        {
            const float* rp = raw + lrow * 128;
            float vv[16];
            #pragma unroll
            for (int i4 = 0; i4 < 4; i4++) {
                float4 f = *reinterpret_cast<const float4*>(rp + (lsub + 8 * i4) * 4);
                vv[4 * i4] = f.x; vv[4 * i4 + 1] = f.y; vv[4 * i4 + 2] = f.z; vv[4 * i4 + 3] = f.w;
            }
            float s = 0.f;
            #pragma unroll
            for (int i2 = 0; i2 < 16; i2++) s += vv[i2];
            #pragma unroll
            for (int o = 1; o < 8; o <<= 1) s += __shfl_xor_sync(0xffffffffu, s, o);
            float mu = s * (1.0f / 128.0f);
            float q2 = 0.f;
            #pragma unroll
            for (int i2 = 0; i2 < 16; i2++) { float d = vv[i2] - mu; q2 += d * d; }
            #pragma unroll
            for (int o = 1; o < 8; o <<= 1) q2 += __shfl_xor_sync(0xffffffffu, q2, o);
            float rs = rsqrtf(q2 * (1.0f / 128.0f) + 1e-5f);
            unsigned* xw = reinterpret_cast<unsigned*>(sX) + lrow * 68;
            #pragma unroll
            for (int i4 = 0; i4 < 4; i4++) {
                int c0 = lsub * 4 + i4 * 32;
                float a0 = (vv[4 * i4]     - mu) * rs * lnqg[c0]     + lnqb[c0];
                float a1 = (vv[4 * i4 + 1] - mu) * rs * lnqg[c0 + 1] + lnqb[c0 + 1];
                float a2 = (vv[4 * i4 + 2] - mu) * rs * lnqg[c0 + 2] + lnqb[c0 + 2];
                float a3 = (vv[4 * i4 + 3] - mu) * rs * lnqg[c0 + 3] + lnqb[c0 + 3];
                xw[2 * lsub + 16 * i4]     = pk(a0, a1);
                xw[2 * lsub + 16 * i4 + 1] = pk(a2, a3);
            }
        }
        __syncthreads();
        if (j == 0) cpa_wait<0>();              // wq must be resident before GEMM
        if (j < 11) {
            int j2 = j + 1;
            int qc2 = (j2 < 6) ? 2 * j2 : 2 * j2 - 11;
            stage_chunk(raw, q, l, qc2 * 32, 6, 63, tid);
            cpa_commit();
        }

        // q GEMM
        float acc[4][4] = {};
        #pragma unroll
        for (int kk = 0; kk < 128; kk += 16) {
            unsigned uoff = ((((kk >> 3) + wu0) ^ wrx) << 4);
            unsigned a[4], b01[4], b23[4];
            ldsm4(a, abase + kk * 2);
            ldsm4(b01, wrow01 + uoff);
            ldsm4(b23, wrow23 + uoff);
            mma16816(acc[0], a, &b01[0]);
            mma16816(acc[1], a, &b01[2]);
            mma16816(acc[2], a, &b23[0]);
            mma16816(acc[3], a, &b23[2]);
        }

        // epilogue: +bias -> RoPE -> *scale -> A fragments
        unsigned aq0[4], aq1[4];
        {
            float F[4][4];
            #pragma unroll
            for (int r = 0; r < 2; r++) {
                int t = qc * 32 + mrow + gq + 8 * r;
                #pragma unroll
                for (int ntl = 0; ntl < 2; ntl++) {
                    int jlo = ntl * 8 + 2 * t4;
                    int jhi = jlo + 16;
                    float2 blo = *reinterpret_cast<const float2*>(&bq[mh * 32 + jlo]);
                    float2 bhi = *reinterpret_cast<const float2*>(&bq[mh * 32 + jhi]);
                    float plo0 = acc[ntl][2 * r] + blo.x;
                    float plo1 = acc[ntl][2 * r + 1] + blo.y;
                    float phi0 = acc[ntl + 2][2 * r] + bhi.x;
                    float phi1 = acc[ntl + 2][2 * r + 1] + bhi.y;
                    float2 cl = *reinterpret_cast<const float2*>(&g_cos[t * 32 + jlo]);
                    float2 sl = *reinterpret_cast<const float2*>(&g_sin[t * 32 + jlo]);
                    float2 ch = *reinterpret_cast<const float2*>(&g_cos[t * 32 + jhi]);
                    float2 sh = *reinterpret_cast<const float2*>(&g_sin[t * 32 + jhi]);
                    F[ntl][2 * r]         = (plo0 * cl.x - phi0 * sl.x) * sc;
                    F[ntl][2 * r + 1]     = (plo1 * cl.y - phi1 * sl.y) * sc;
                    F[ntl + 2][2 * r]     = (phi0 * ch.x + plo0 * sh.x) * sc;
                    F[ntl + 2][2 * r + 1] = (phi1 * ch.y + plo1 * sh.y) * sc;
                }
            }
            aq0[0] = pk(F[0][0], F[0][1]); aq0[1] = pk(F[0][2], F[0][3]);
            aq0[2] = pk(F[1][0], F[1][1]); aq0[3] = pk(F[1][2], F[1][3]);
            aq1[0] = pk(F[2][0], F[2][1]); aq1[1] = pk(F[2][2], F[2][3]);
            aq1[2] = pk(F[3][0], F[3][1]); aq1[3] = pk(F[3][2], F[3][3]);
        }

        // S = Q K^T over 96 keys
        float sacc[12][4] = {};
        #pragma unroll
        for (int p = 0; p < 6; p++) {
            unsigned b[4];
            ldsm4(b, kb[p]);
            mma16816(sacc[2 * p], aq0, &b[0]);
            mma16816(sacc[2 * p + 1], aq0, &b[2]);
        }
        #pragma unroll
        for (int p = 0; p < 6; p++) {
            unsigned b[4];
            ldsm4(b, kb[p] + 32);
            mma16816(sacc[2 * p], aq1, &b[0]);
            mma16816(sacc[2 * p + 1], aq1, &b[2]);
        }

        // softmax over 96
        float mx0 = -1e30f, mx1 = -1e30f;
        #pragma unroll
        for (int nt = 0; nt < 12; nt++) {
            mx0 = fmaxf(mx0, fmaxf(sacc[nt][0], sacc[nt][1]));
            mx1 = fmaxf(mx1, fmaxf(sacc[nt][2], sacc[nt][3]));
        }
        mx0 = fmaxf(mx0, __shfl_xor_sync(0xffffffffu, mx0, 1));
        mx0 = fmaxf(mx0, __shfl_xor_sync(0xffffffffu, mx0, 2));
        mx1 = fmaxf(mx1, __shfl_xor_sync(0xffffffffu, mx1, 1));
        mx1 = fmaxf(mx1, __shfl_xor_sync(0xffffffffu, mx1, 2));
        float sm0 = 0.f, sm1 = 0.f;
        #pragma unroll
        for (int nt = 0; nt < 12; nt++) {
            sacc[nt][0] = __expf(sacc[nt][0] - mx0);
            sacc[nt][1] = __expf(sacc[nt][1] - mx0);
            sacc[nt][2] = __expf(sacc[nt][2] - mx1);
            sacc[nt][3] = __expf(sacc[nt][3] - mx1);
            sm0 += sacc[nt][0] + sacc[nt][1];
            sm1 += sacc[nt][2] + sacc[nt][3];
        }
        sm0 += __shfl_xor_sync(0xffffffffu, sm0, 1);
        sm0 += __shfl_xor_sync(0xffffffffu, sm0, 2);
        sm1 += __shfl_xor_sync(0xffffffffu, sm1, 1);
        sm1 += __shfl_xor_sync(0xffffffffu, sm1, 2);
        float r0i = 1.0f / sm0, r1i = 1.0f / sm1;
        #pragma unroll
        for (int nt = 0; nt < 12; nt++) {
            sacc[nt][0] *= r0i; sacc[nt][1] *= r0i;
            sacc[nt][2] *= r1i; sacc[nt][3] *= r1i;
        }

        // O += P V (accumulates over the 6 views of this uv-half)
        #pragma unroll
        for (int c6 = 0; c6 < 6; c6++) {
            unsigned a[4];
            a[0] = pk(sacc[2 * c6][0], sacc[2 * c6][1]);
            a[1] = pk(sacc[2 * c6][2], sacc[2 * c6][3]);
            a[2] = pk(sacc[2 * c6 + 1][0], sacc[2 * c6 + 1][1]);
            a[3] = pk(sacc[2 * c6 + 1][2], sacc[2 * c6 + 1][3]);
            #pragma unroll
            for (int p = 0; p < 2; p++) {
                unsigned b[4];
                ldsm4(b, vb[p] + c6 * 32);
                mma16816(moacc[2 * p], a, &b[0]);
                mma16816(moacc[2 * p + 1], a, &b[2]);
            }
        }

        if (j == 5) {
            // flush even uv-half mean to global scratch; reset accumulator
            #pragma unroll
            for (int nt = 0; nt < 4; nt++) {
                int col = mh * 32 + nt * 8 + 2 * t4;
                #pragma unroll
                for (int r = 0; r < 2; r++) {
                    int uv = mrow + gq + 8 * r;
                    *reinterpret_cast<unsigned*>(g_tmp + (size_t)l * 4096 + uv * 128 + col) =
                        pk(moacc[nt][2 * r] * (1.0f / 6.0f), moacc[nt][2 * r + 1] * (1.0f / 6.0f));
                }
            }
            #pragma unroll
            for (int nt = 0; nt < 4; nt++)
                #pragma unroll
                for (int e = 0; e < 4; e++) moacc[nt][e] = 0.f;
        }
    }

    // =========================== Phase C: mean -> proj -> +skip -> out ===========================
    __syncthreads();   // all attention reads of sK/sVt/sW/raw done

    // odd uv-half: registers -> rawO rows 32..63 (swizzled bf16 64x128)
    #pragma unroll
    for (int nt = 0; nt < 4; nt++) {
        int col = mh * 32 + nt * 8 + 2 * t4;
        int cu = col >> 3;
        #pragma unroll
        for (int r = 0; r < 2; r++) {
            int row = 32 + mrow + gq + 8 * r;
            *reinterpret_cast<unsigned*>(&rawO[row * 128 + ((cu ^ (row & 7)) << 3) + (col & 7)]) =
                pk(moacc[nt][2 * r] * (1.0f / 6.0f), moacc[nt][2 * r + 1] * (1.0f / 6.0f));
        }
    }
    // stage wp, even uv-half (g_tmp), skip
    stage_w(sW, g_wp, tid);
    #pragma unroll
    for (int u = tid; u < 512; u += 256) {
        int row = u >> 4, cu = u & 15;
        cpa16(&rawO[row * 128 + ((cu ^ (row & 7)) << 3)],
              g_tmp + (size_t)l * 4096 + row * 128 + cu * 8);
    }
    float* sSkip = reinterpret_cast<float*>(sm + E_K);   // 32 KB inside dead sK/sVt region
    #pragma unroll
    for (int u = tid; u < 2048; u += 256)
        cpa16(sSkip + u * 4, skip + (size_t)l * 8192 + u * 4);
    cpa_commit();
    cpa_wait<0>();
    __syncthreads();

    // proj GEMM: 64 rows x 128 cols; warp = (rh = wid&3 rowtile, cg = wid>>2 colgroup of 64)
    {
        int rh = wid & 3, cg = wid >> 2;
        int prowA = rh * 16 + (lane & 15);
        unsigned paRow = ssa(rawO) + prowA * 256;
        int parx = prowA & 7, pau0 = lane >> 4;
        int op = cg * 64 + ((lane >> 4) << 3) + (lane & 7);
        unsigned pw0 = sWb + op * 256;
        int prx = op & 7;
        float pacc[8][4] = {};
        #pragma unroll
        for (int kk = 0; kk < 128; kk += 16) {
            unsigned a[4];
            ldsm4(a, paRow + ((((kk >> 3) + pau0) ^ parx) << 4));
            unsigned uoff = ((((kk >> 3) + wu0) ^ prx) << 4);
            #pragma unroll
            for (int p = 0; p < 4; p++) {
                unsigned b[4];
                ldsm4(b, pw0 + p * 4096 + uoff);
                mma16816(pacc[2 * p], a, &b[0]);
                mma16816(pacc[2 * p + 1], a, &b[2]);
            }
        }
        #pragma unroll
        for (int nt = 0; nt < 8; nt++) {
            int col = cg * 64 + nt * 8 + 2 * t4;
            float2 bp = *reinterpret_cast<const float2*>(&bproj[col]);
            #pragma unroll
            for (int r = 0; r < 2; r++) {
                int rloc = rh * 16 + gq + 8 * r;
                float2 sk = *reinterpret_cast<const float2*>(sSkip + rloc * 128 + col);
                float2 o2;
                o2.x = pacc[nt][2 * r] + bp.x + sk.x;
                o2.y = pacc[nt][2 * r + 1] + bp.y + sk.y;
                *reinterpret_cast<float2*>(out + ((size_t)l * 64 + rloc) * 128 + col) = o2;
            }
        }
    }
}

// ---------------- launch ----------------
extern "C" void kernel_launch(void* const* d_in, const int* in_sizes, int n_in,
                              void* d_out, int out_size) {
    const float* q     = (const float*)d_in[0];
    const float* k     = (const float*)d_in[1];
    const float* v     = (const float*)d_in[2];
    const float* skip  = (const float*)d_in[3];
    const float* freqs = (const float*)d_in[4];
    const float* gate  = (const float*)d_in[5];
    const float* lnqg  = (const float*)d_in[6];
    const float* lnqb  = (const float*)d_in[7];
    const float* lnkg  = (const float*)d_in[8];
    const float* lnkb  = (const float*)d_in[9];
    const float* lnvg  = (const float*)d_in[10];
    const float* lnvb  = (const float*)d_in[11];
    const float* wq    = (const float*)d_in[12];
    const float* bq    = (const float*)d_in[13];
    const float* wk    = (const float*)d_in[14];
    const float* bk    = (const float*)d_in[15];
    const float* wv    = (const float*)d_in[16];
    const float* bv    = (const float*)d_in[17];
    const float* wproj = (const float*)d_in[18];
    const float* bproj = (const float*)d_in[19];
    const float* als   = (const float*)d_in[20];
    float* out = (float*)d_out;

    static int smem_set = 0;
    if (!smem_set) {
        cudaFuncSetAttribute(fused_kernel, cudaFuncAttributeMaxDynamicSharedMemorySize, SMEM_BYTES);
        smem_set = 1;
    }

    prep_const_kernel<<<305, 256>>>(wq, wk, wv, wproj, freqs, gate, als);
    fused_kernel<<<LTOT, 256, SMEM_BYTES>>>(q, k, v, skip,
                                            lnqg, lnqb, lnkg, lnkb, lnvg, lnvb,
                                            bq, bk, bv, bproj, out);
}

// round 8
// speedup vs baseline: 1.3256x; 1.1977x over previous
#include <cuda_runtime.h>
#include <cuda_bf16.h>
#include <math.h>

// ---------------- problem constants ----------------
// B=1, N=6, X=Y=25 (L=625), W1=W2=8 (Qn=384), w1=w2=4 (Kn=96), D=128, M=4 heads, dh=32

#define LTOT 625
#define QN   384

// ---------------- device constants / scratch ----------------
__device__ __nv_bfloat16 g_wq[16384];
__device__ __nv_bfloat16 g_wk[16384];
__device__ __nv_bfloat16 g_wv[16384];
__device__ __nv_bfloat16 g_wp[16384];
__device__ __nv_bfloat16 g_tmp[(size_t)LTOT * 32 * 128];   // even-half O-mean spill
__device__ unsigned g_csb[QN * 32];                        // packed bf16x2 (cos, sin)
__device__ float g_scales[4];

// ---------------- helpers ----------------
__device__ __forceinline__ unsigned pk(float a, float b) {
    __nv_bfloat162 h = __floats2bfloat162_rn(a, b);
    return *reinterpret_cast<unsigned*>(&h);
}
__device__ __forceinline__ float2 bf2f(unsigned u) {
    __nv_bfloat162 h = *reinterpret_cast<__nv_bfloat162*>(&u);
    return __bfloat1622float2(h);
}
__device__ __forceinline__ float ex2(float x) {
    float y;
    asm("ex2.approx.ftz.f32 %0, %1;\n" : "=f"(y) : "f"(x));
    return y;
}
__device__ __forceinline__ unsigned ssa(const void* p) {
    return (unsigned)__cvta_generic_to_shared(p);
}
__device__ __forceinline__ void ldsm4(unsigned r[4], unsigned addr) {
    asm volatile("ldmatrix.sync.aligned.m8n8.x4.shared.b16 {%0,%1,%2,%3}, [%4];\n"
                 : "=r"(r[0]), "=r"(r[1]), "=r"(r[2]), "=r"(r[3]) : "r"(addr));
}
__device__ __forceinline__ void mma16816(float c[4], const unsigned a[4], const unsigned b[2]) {
    asm volatile(
        "mma.sync.aligned.m16n8k16.row.col.f32.bf16.bf16.f32 "
        "{%0,%1,%2,%3}, {%4,%5,%6,%7}, {%8,%9}, {%0,%1,%2,%3};\n"
        : "+f"(c[0]), "+f"(c[1]), "+f"(c[2]), "+f"(c[3])
        : "r"(a[0]), "r"(a[1]), "r"(a[2]), "r"(a[3]), "r"(b[0]), "r"(b[1]));
}
__device__ __forceinline__ void cpa16(void* dst, const void* src) {
    asm volatile("cp.async.cg.shared.global [%0], [%1], 16;\n"
                 :: "r"(ssa(dst)), "l"(src));
}
__device__ __forceinline__ void cpa_commit() {
    asm volatile("cp.async.commit_group;\n");
}
template<int N> __device__ __forceinline__ void cpa_wait() {
    asm volatile("cp.async.wait_group %0;\n" :: "n"(N));
}

// ---------------- kernel 0: constants prep ----------------
__global__ __launch_bounds__(256) void prep_const_kernel(
    const float* __restrict__ wq, const float* __restrict__ wk,
    const float* __restrict__ wv, const float* __restrict__ wp,
    const float* __restrict__ freqs, const float* __restrict__ gate,
    const float* __restrict__ als)
{
    int idx = blockIdx.x * 256 + threadIdx.x;
    if (idx < 16384) {
        g_wq[idx] = __float2bfloat16(wq[idx]);
    } else if (idx < 32768) {
        g_wk[idx - 16384] = __float2bfloat16(wk[idx - 16384]);
    } else if (idx < 49152) {
        g_wv[idx - 32768] = __float2bfloat16(wv[idx - 32768]);
    } else if (idx < 65536) {
        g_wp[idx - 49152] = __float2bfloat16(wp[idx - 49152]);
    } else if (idx < 65536 + QN * 32) {
        int j = idx - 65536;
        float f = freqs[j];            // (400,32) row-major, t<384 prefix
        g_csb[j] = pk(cosf(f), sinf(f));
    } else if (idx < 65536 + QN * 32 + 4) {
        int m = idx - (65536 + QN * 32);
        float temp = als[m] - 0.5f * logf(32.0f);   // als + log(dh^-0.5)
        float ga = fminf(fmaxf(gate[m], 0.0f), 1.0f);
        g_scales[m] = temp * ga * 1.44269504f;      // fold log2(e): ex2 later
    }
}

// ---------------- smem layout (bf16 element offsets) ----------------
// sK   : 4*96*32 = 12288   K per head, SW64-XOR-swizzled (64B rows)
// sVt  : 4*32*104 = 13312  V^T[d][s] padded stride 104, per head
// sW   : 128*128 = 16384   weights, XOR-swizzled 16B units
// raw  : 8192 elems (16 KB) fp32 LN staging 32x128; Phase C: bf16 O 64x128 swizzled
// sCS  : 2048 elems (4 KB)  packed bf16x2 (cos,sin) for current 32-row chunk
// sX   : 32*136 = 4352     LN bf16 output staging
#define E_K   0
#define E_VT  12288
#define E_W   25600
#define E_RAW 41984
#define E_CS  50176
#define E_X   52224
#define SMEM_ELEMS 56576
#define SMEM_BYTES (SMEM_ELEMS * 2)   // 113152 -> 2 blocks/SM

__device__ __forceinline__ void stage_w(__nv_bfloat16* sW, const __nv_bfloat16* w, int tid) {
    #pragma unroll
    for (int u = tid; u < 2048; u += 256) {
        int row = u >> 4, cu = u & 15;
        cpa16(sW + row * 128 + ((cu ^ (row & 7)) << 3), w + u * 8);
    }
}
__device__ __forceinline__ void stage_chunk(float* raw, const float* x, int l,
                                            int t0, int sh, int msk, int tid) {
    #pragma unroll
    for (int j = 0; j < 4; j++) {
        int idx = tid + 256 * j;
        int row = idx >> 5, c4 = idx & 31;
        int t = t0 + row;
        int n = t >> sh, rem = t & msk;
        cpa16(raw + row * 128 + c4 * 4,
              x + ((size_t)(n * LTOT + l) * (msk + 1) + rem) * 128 + c4 * 4);
    }
}
__device__ __forceinline__ void stage_cs(unsigned* sCS, const unsigned* src, int tid) {
    cpa16(sCS + tid * 4, src + tid * 4);   // 256 threads x 16B = 4 KB
}

// ---------------- fused kernel: one block per l-tile, 2 blocks/SM ----------------
__global__ __launch_bounds__(256, 2) void fused_kernel(
    const float* __restrict__ q, const float* __restrict__ k,
    const float* __restrict__ v, const float* __restrict__ skip,
    const float* __restrict__ lnqg, const float* __restrict__ lnqb,
    const float* __restrict__ lnkg, const float* __restrict__ lnkb,
    const float* __restrict__ lnvg, const float* __restrict__ lnvb,
    const float* __restrict__ bq, const float* __restrict__ bk,
    const float* __restrict__ bv, const float* __restrict__ bproj,
    float* __restrict__ out)
{
    extern __shared__ __nv_bfloat16 sm[];
    __nv_bfloat16* sK  = sm + E_K;
    __nv_bfloat16* sVt = sm + E_VT;
    __nv_bfloat16* sW  = sm + E_W;
    float* raw = reinterpret_cast<float*>(sm + E_RAW);
    __nv_bfloat16* rawO = sm + E_RAW;
    unsigned* sCS = reinterpret_cast<unsigned*>(sm + E_CS);
    __nv_bfloat16* sX  = sm + E_X;

    int l = blockIdx.x;
    int tid = threadIdx.x;
    int wid = tid >> 5, lane = tid & 31, gq = lane >> 2, t4 = lane & 3;
    int mrow = (wid & 1) * 16;            // 16-row half within 32-row chunk
    int mh = wid >> 1;                    // head
    int lrow = tid >> 3, lsub = tid & 7;  // LN: 8 threads/row

    unsigned sWb = ssa(sW);
    unsigned abase = ssa(&sX[(mrow + (lane & 15)) * 136 + ((lane >> 4) << 3)]);

    // weight B-fragment lane constants (swizzled sW; 16B units, row stride 256 B)
    int o01 = mh * 32 + ((lane >> 4) << 3) + (lane & 7);
    unsigned wrow01 = sWb + o01 * 256;
    unsigned wrow23 = wrow01 + 4096;      // +16 output rows
    int wrx = o01 & 7;
    int wu0 = (lane >> 3) & 1;

    // K fragment bases (SW64-swizzled sK): second kk block = addr ^ 32
    char* sKb = reinterpret_cast<char*>(sK) + mh * 6144;
    unsigned kb0[6];
    {
        unsigned sKhb = ssa(sKb);
        int u0 = (lane >> 3) & 1;
        #pragma unroll
        for (int p = 0; p < 6; p++) {
            int tr = (2 * p + (lane >> 4)) * 8 + (lane & 7);
            kb0[p] = sKhb + tr * 64 + ((u0 ^ ((tr >> 1) & 3)) << 4);
        }
    }
    // V^T fragment bases (padded stride 104)
    __nv_bfloat16* sVh = sVt + mh * 32 * 104;
    unsigned vb[2];
    #pragma unroll
    for (int p = 0; p < 2; p++)
        vb[p] = ssa(&sVh[((2 * p + (lane >> 4)) * 8 + (lane & 7)) * 104 + (((lane >> 3) & 1) << 3)]);
    float sc = g_scales[mh];

    // initial: wk + first k chunk
    stage_w(sW, g_wk, tid);
    cpa_commit();
    stage_chunk(raw, k, l, 0, 4, 15, tid);
    cpa_commit();

    // =========================== Phase A: K (i=0..2) then V (i=3..5) prep ===========================
    for (int i = 0; i < 6; i++) {
        int isV = (i >= 3);
        cpa_wait<0>();
        __syncthreads();                        // chunk i arrived; prev epilogue reads of sCS done
        if (i < 3) { stage_cs(sCS, g_csb + i * 32 * 32, tid); cpa_commit(); }  // [A]
        if (i == 3) { stage_w(sW, g_wv, tid); cpa_commit(); }                  // [W]

        // LayerNorm 32 rows
        {
            const float* lng  = isV ? lnvg : lnkg;
            const float* lnb_ = isV ? lnvb : lnkb;
            const float* rp = raw + lrow * 128;
            float vv[16];
            #pragma unroll
            for (int i4 = 0; i4 < 4; i4++) {
                float4 f = *reinterpret_cast<const float4*>(rp + (lsub + 8 * i4) * 4);
                vv[4 * i4] = f.x; vv[4 * i4 + 1] = f.y; vv[4 * i4 + 2] = f.z; vv[4 * i4 + 3] = f.w;
            }
            float s = 0.f;
            #pragma unroll
            for (int i2 = 0; i2 < 16; i2++) s += vv[i2];
            #pragma unroll
            for (int o = 1; o < 8; o <<= 1) s += __shfl_xor_sync(0xffffffffu, s, o);
            float mu = s * (1.0f / 128.0f);
            float q2 = 0.f;
            #pragma unroll
            for (int i2 = 0; i2 < 16; i2++) { float d = vv[i2] - mu; q2 += d * d; }
            #pragma unroll
            for (int o = 1; o < 8; o <<= 1) q2 += __shfl_xor_sync(0xffffffffu, q2, o);
            float rs = rsqrtf(q2 * (1.0f / 128.0f) + 1e-5f);
            unsigned* xw = reinterpret_cast<unsigned*>(sX) + lrow * 68;
            #pragma unroll
            for (int i4 = 0; i4 < 4; i4++) {
                int c0 = lsub * 4 + i4 * 32;
                float a0 = (vv[4 * i4]     - mu) * rs * lng[c0]     + lnb_[c0];
                float a1 = (vv[4 * i4 + 1] - mu) * rs * lng[c0 + 1] + lnb_[c0 + 1];
                float a2 = (vv[4 * i4 + 2] - mu) * rs * lng[c0 + 2] + lnb_[c0 + 2];
                float a3 = (vv[4 * i4 + 3] - mu) * rs * lng[c0 + 3] + lnb_[c0 + 3];
                xw[2 * lsub + 16 * i4]     = pk(a0, a1);
                xw[2 * lsub + 16 * i4 + 1] = pk(a2, a3);
            }
        }
        __syncthreads();                        // raw free, sX ready
        if (i == 3) cpa_wait<0>();              // wv must be resident before GEMM
        // prefetch next chunk into raw                                        // [B]
        if (i < 2)       stage_chunk(raw, k, l, (i + 1) * 32, 4, 15, tid);
        else if (i < 5)  stage_chunk(raw, v, l, (i - 2) * 32, 4, 15, tid);
        else             stage_chunk(raw, q, l, 0, 6, 63, tid);
        cpa_commit();

        // GEMM: 32 rows x 128 cols
        float acc[4][4] = {};
        #pragma unroll
        for (int kk = 0; kk < 128; kk += 16) {
            unsigned uoff = ((((kk >> 3) + wu0) ^ wrx) << 4);
            unsigned a[4], b01[4], b23[4];
            ldsm4(a, abase + kk * 2);
            ldsm4(b01, wrow01 + uoff);
            ldsm4(b23, wrow23 + uoff);
            mma16816(acc[0], a, &b01[0]);
            mma16816(acc[1], a, &b01[2]);
            mma16816(acc[2], a, &b23[0]);
            mma16816(acc[3], a, &b23[2]);
        }
        cpa_wait<1>();                          // cs chunk arrived (no-op for V iters)

        if (!isV) {
            // K: +bias -> RoPE(bf16 trig from sCS) -> sK (SW64 swizzled)
            #pragma unroll
            for (int r = 0; r < 2; r++) {
                int lt = mrow + gq + 8 * r;
                int t = i * 32 + lt;
                #pragma unroll
                for (int ntl = 0; ntl < 2; ntl++) {
                    int jlo = ntl * 8 + 2 * t4;
                    int jhi = jlo + 16;
                    float2 blo = *reinterpret_cast<const float2*>(&bk[mh * 32 + jlo]);
                    float2 bhi = *reinterpret_cast<const float2*>(&bk[mh * 32 + jhi]);
                    float plo0 = acc[ntl][2 * r] + blo.x;
                    float plo1 = acc[ntl][2 * r + 1] + blo.y;
                    float phi0 = acc[ntl + 2][2 * r] + bhi.x;
                    float phi1 = acc[ntl + 2][2 * r + 1] + bhi.y;
                    uint2 ulo = *reinterpret_cast<const uint2*>(&sCS[lt * 32 + jlo]);
                    uint2 uhi = *reinterpret_cast<const uint2*>(&sCS[lt * 32 + jhi]);
                    float2 cs0 = bf2f(ulo.x), cs1 = bf2f(ulo.y);
                    float2 cs2 = bf2f(uhi.x), cs3 = bf2f(uhi.y);
                    unsigned off0 = t * 64 + jlo * 2;
                    unsigned off1 = t * 64 + jhi * 2;
                    *reinterpret_cast<unsigned*>(sKb + (off0 ^ ((off0 >> 3) & 0x30))) =
                        pk(plo0 * cs0.x - phi0 * cs0.y, plo1 * cs1.x - phi1 * cs1.y);
                    *reinterpret_cast<unsigned*>(sKb + (off1 ^ ((off1 >> 3) & 0x30))) =
                        pk(phi0 * cs2.x + plo0 * cs2.y, phi1 * cs3.x + plo1 * cs3.y);
                }
            }
        } else {
            // V: +bias -> transpose into sVt
            #pragma unroll
            for (int r = 0; r < 2; r++) {
                int t = (i - 3) * 32 + mrow + gq + 8 * r;
                #pragma unroll
                for (int ntl = 0; ntl < 2; ntl++) {
                    int jlo = ntl * 8 + 2 * t4;
                    int jhi = jlo + 16;
                    float2 blo = *reinterpret_cast<const float2*>(&bv[mh * 32 + jlo]);
                    float2 bhi = *reinterpret_cast<const float2*>(&bv[mh * 32 + jhi]);
                    sVt[(mh * 32 + jlo) * 104 + t]     = __float2bfloat16(acc[ntl][2 * r] + blo.x);
                    sVt[(mh * 32 + jlo + 1) * 104 + t] = __float2bfloat16(acc[ntl][2 * r + 1] + blo.y);
                    sVt[(mh * 32 + jhi) * 104 + t]     = __float2bfloat16(acc[ntl + 2][2 * r] + bhi.x);
                    sVt[(mh * 32 + jhi + 1) * 104 + t] = __float2bfloat16(acc[ntl + 2][2 * r + 1] + bhi.y);
                }
            }
        }
    }

    // =========================== Phase B: Q prep + attention + mean ===========================
    float moacc[4][4] = {};

    for (int j = 0; j < 12; j++) {
        int qc = (j < 6) ? 2 * j : 2 * j - 11;   // even uv-half first, then odd
        cpa_wait<0>();
        __syncthreads();                          // raw_j arrived; prev sCS reads done
        stage_cs(sCS, g_csb + qc * 32 * 32, tid); cpa_commit();       // [A]
        if (j == 0) { stage_w(sW, g_wq, tid); cpa_commit(); }         // [W]

        // LayerNorm (q)
        {
            const float* rp = raw + lrow * 128;
            float vv[16];
            #pragma unroll
            for (int i4 = 0; i4 < 4; i4++) {
                float4 f = *reinterpret_cast<const float4*>(rp + (lsub + 8 * i4) * 4);
                vv[4 * i4] = f.x; vv[4 * i4 + 1] = f.y; vv[4 * i4 + 2] = f.z; vv[4 * i4 + 3] = f.w;
            }
            float s = 0.f;
            #pragma unroll
            for (int i2 = 0; i2 < 16; i2++) s += vv[i2];
            #pragma unroll
            for (int o = 1; o < 8; o <<= 1) s += __shfl_xor_sync(0xffffffffu, s, o);
            float mu = s * (1.0f / 128.0f);
            float q2 = 0.f;
            #pragma unroll
            for (int i2 = 0; i2 < 16; i2++) { float d = vv[i2] - mu; q2 += d * d; }
            #pragma unroll
            for (int o = 1; o < 8; o <<= 1) q2 += __shfl_xor_sync(0xffffffffu, q2, o);
            float rs = rsqrtf(q2 * (1.0f / 128.0f) + 1e-5f);
            unsigned* xw = reinterpret_cast<unsigned*>(sX) + lrow * 68;
            #pragma unroll
            for (int i4 = 0; i4 < 4; i4++) {
                int c0 = lsub * 4 + i4 * 32;
                float a0 = (vv[4 * i4]     - mu) * rs * lnqg[c0]     + lnqb[c0];
                float a1 = (vv[4 * i4 + 1] - mu) * rs * lnqg[c0 + 1] + lnqb[c0 + 1];
                float a2 = (vv[4 * i4 + 2] - mu) * rs * lnqg[c0 + 2] + lnqb[c0 + 2];
                float a3 = (vv[4 * i4 + 3] - mu) * rs * lnqg[c0 + 3] + lnqb[c0 + 3];
                xw[2 * lsub + 16 * i4]     = pk(a0, a1);
                xw[2 * lsub + 16 * i4 + 1] = pk(a2, a3);
            }
        }
        __syncthreads();
        if (j == 0) cpa_wait<0>();              // wq resident before GEMM
        if (j < 11) {
            int j2 = j + 1;
            int qc2 = (j2 < 6) ? 2 * j2 : 2 * j2 - 11;
            stage_chunk(raw, q, l, qc2 * 32, 6, 63, tid);             // [B]
            cpa_commit();
        }

        // q GEMM
        float acc[4][4] = {};
        #pragma unroll
        for (int kk = 0; kk < 128; kk += 16) {
            unsigned uoff = ((((kk >> 3) + wu0) ^ wrx) << 4);
            unsigned a[4], b01[4], b23[4];
            ldsm4(a, abase + kk * 2);
            ldsm4(b01, wrow01 + uoff);
            ldsm4(b23, wrow23 + uoff);
            mma16816(acc[0], a, &b01[0]);
            mma16816(acc[1], a, &b01[2]);
            mma16816(acc[2], a, &b23[0]);
            mma16816(acc[3], a, &b23[2]);
        }
        if (j < 11) cpa_wait<1>(); else cpa_wait<0>();   // cs arrived

        // epilogue: +bias -> RoPE(bf16 trig) -> *scale(log2e folded) -> A fragments
        unsigned aq0[4], aq1[4];
        {
            float F[4][4];
            #pragma unroll
            for (int r = 0; r < 2; r++) {
                int lt = mrow + gq + 8 * r;
                #pragma unroll
                for (int ntl = 0; ntl < 2; ntl++) {
                    int jlo = ntl * 8 + 2 * t4;
                    int jhi = jlo + 16;
                    float2 blo = *reinterpret_cast<const float2*>(&bq[mh * 32 + jlo]);
                    float2 bhi = *reinterpret_cast<const float2*>(&bq[mh * 32 + jhi]);
                    float plo0 = acc[ntl][2 * r] + blo.x;
                    float plo1 = acc[ntl][2 * r + 1] + blo.y;
                    float phi0 = acc[ntl + 2][2 * r] + bhi.x;
                    float phi1 = acc[ntl + 2][2 * r + 1] + bhi.y;
                    uint2 ulo = *reinterpret_cast<const uint2*>(&sCS[lt * 32 + jlo]);
                    uint2 uhi = *reinterpret_cast<const uint2*>(&sCS[lt * 32 + jhi]);
                    float2 cs0 = bf2f(ulo.x), cs1 = bf2f(ulo.y);
                    float2 cs2 = bf2f(uhi.x), cs3 = bf2f(uhi.y);
                    F[ntl][2 * r]         = (plo0 * cs0.x - phi0 * cs0.y) * sc;
                    F[ntl][2 * r + 1]     = (plo1 * cs1.x - phi1 * cs1.y) * sc;
                    F[ntl + 2][2 * r]     = (phi0 * cs2.x + plo0 * cs2.y) * sc;
                    F[ntl + 2][2 * r + 1] = (phi1 * cs3.x + plo1 * cs3.y) * sc;
                }
            }
            aq0[0] = pk(F[0][0], F[0][1]); aq0[1] = pk(F[0][2], F[0][3]);
            aq0[2] = pk(F[1][0], F[1][1]); aq0[3] = pk(F[1][2], F[1][3]);
            aq1[0] = pk(F[2][0], F[2][1]); aq1[1] = pk(F[2][2], F[2][3]);
            aq1[2] = pk(F[3][0], F[3][1]); aq1[3] = pk(F[3][2], F[3][3]);
        }

        // S = Q K^T over 96 keys (SW64-swizzled K; kk block 1 = addr ^ 32)
        float sacc[12][4] = {};
        #pragma unroll
        for (int p = 0; p < 6; p++) {
            unsigned b[4];
            ldsm4(b, kb0[p]);
            mma16816(sacc[2 * p], aq0, &b[0]);
            mma16816(sacc[2 * p + 1], aq0, &b[2]);
        }
        #pragma unroll
        for (int p = 0; p < 6; p++) {
            unsigned b[4];
            ldsm4(b, kb0[p] ^ 32u);
            mma16816(sacc[2 * p], aq1, &b[0]);
            mma16816(sacc[2 * p + 1], aq1, &b[2]);
        }

        // softmax over 96: no max pass (logits bounded), base-2 exp, 1/6 folded
        float sm0 = 0.f, sm1 = 0.f;
        #pragma unroll
        for (int nt = 0; nt < 12; nt++) {
            sacc[nt][0] = ex2(sacc[nt][0]);
            sacc[nt][1] = ex2(sacc[nt][1]);
            sacc[nt][2] = ex2(sacc[nt][2]);
            sacc[nt][3] = ex2(sacc[nt][3]);
            sm0 += sacc[nt][0] + sacc[nt][1];
            sm1 += sacc[nt][2] + sacc[nt][3];
        }
        sm0 += __shfl_xor_sync(0xffffffffu, sm0, 1);
        sm0 += __shfl_xor_sync(0xffffffffu, sm0, 2);
        sm1 += __shfl_xor_sync(0xffffffffu, sm1, 1);
        sm1 += __shfl_xor_sync(0xffffffffu, sm1, 2);
        float r0i = __fdividef(0.16666667f, sm0);
        float r1i = __fdividef(0.16666667f, sm1);
        #pragma unroll
        for (int nt = 0; nt < 12; nt++) {
            sacc[nt][0] *= r0i; sacc[nt][1] *= r0i;
            sacc[nt][2] *= r1i; sacc[nt][3] *= r1i;
        }

        // O += (P/6) V  -> accumulates the view-mean directly
        #pragma unroll
        for (int c6 = 0; c6 < 6; c6++) {
            unsigned a[4];
            a[0] = pk(sacc[2 * c6][0], sacc[2 * c6][1]);
            a[1] = pk(sacc[2 * c6][2], sacc[2 * c6][3]);
            a[2] = pk(sacc[2 * c6 + 1][0], sacc[2 * c6 + 1][1]);
            a[3] = pk(sacc[2 * c6 + 1][2], sacc[2 * c6 + 1][3]);
            #pragma unroll
            for (int p = 0; p < 2; p++) {
                unsigned b[4];
                ldsm4(b, vb[p] + c6 * 32);
                mma16816(moacc[2 * p], a, &b[0]);
                mma16816(moacc[2 * p + 1], a, &b[2]);
            }
        }

        if (j == 5) {
            // flush even uv-half mean to global scratch; reset accumulator
            #pragma unroll
            for (int nt = 0; nt < 4; nt++) {
                int col = mh * 32 + nt * 8 + 2 * t4;
                #pragma unroll
                for (int r = 0; r < 2; r++) {
                    int uv = mrow + gq + 8 * r;
                    *reinterpret_cast<unsigned*>(g_tmp + (size_t)l * 4096 + uv * 128 + col) =
                        pk(moacc[nt][2 * r], moacc[nt][2 * r + 1]);
                }
            }
            #pragma unroll
            for (int nt = 0; nt < 4; nt++)
                #pragma unroll
                for (int e = 0; e < 4; e++) moacc[nt][e] = 0.f;
        }
    }

    // =========================== Phase C: mean -> proj -> +skip -> out ===========================
    __syncthreads();   // all attention reads of sK/sVt/sW/raw done

    // odd uv-half: registers -> rawO rows 32..63 (swizzled bf16 64x128)
    #pragma unroll
    for (int nt = 0; nt < 4; nt++) {
        int col = mh * 32 + nt * 8 + 2 * t4;
        int cu = col >> 3;
        #pragma unroll
        for (int r = 0; r < 2; r++) {
            int row = 32 + mrow + gq + 8 * r;
            *reinterpret_cast<unsigned*>(&rawO[row * 128 + ((cu ^ (row & 7)) << 3) + (col & 7)]) =
                pk(moacc[nt][2 * r], moacc[nt][2 * r + 1]);
        }
    }
    // stage wp, even uv-half (g_tmp), skip
    stage_w(sW, g_wp, tid);
    #pragma unroll
    for (int u = tid; u < 512; u += 256) {
        int row = u >> 4, cu = u & 15;
        cpa16(&rawO[row * 128 + ((cu ^ (row & 7)) << 3)],
              g_tmp + (size_t)l * 4096 + row * 128 + cu * 8);
    }
    float* sSkip = reinterpret_cast<float*>(sm + E_K);   // 32 KB inside dead sK/sVt region
    #pragma unroll
    for (int u = tid; u < 2048; u += 256)
        cpa16(sSkip + u * 4, skip + (size_t)l * 8192 + u * 4);
    cpa_commit();
    cpa_wait<0>();
    __syncthreads();

    // proj GEMM: 64 rows x 128 cols; warp = (rh = wid&3 rowtile, cg = wid>>2 colgroup of 64)
    {
        int rh = wid & 3, cg = wid >> 2;
        int prowA = rh * 16 + (lane & 15);
        unsigned paRow = ssa(rawO) + prowA * 256;
        int parx = prowA & 7, pau0 = lane >> 4;
        int op = cg * 64 + ((lane >> 4) << 3) + (lane & 7);
        unsigned pw0 = sWb + op * 256;
        int prx = op & 7;
        float pacc[8][4] = {};
        #pragma unroll
        for (int kk = 0; kk < 128; kk += 16) {
            unsigned a[4];
            ldsm4(a, paRow + ((((kk >> 3) + pau0) ^ parx) << 4));
            unsigned uoff = ((((kk >> 3) + wu0) ^ prx) << 4);
            #pragma unroll
            for (int p = 0; p < 4; p++) {
                unsigned b[4];
                ldsm4(b, pw0 + p * 4096 + uoff);
                mma16816(pacc[2 * p], a, &b[0]);
                mma16816(pacc[2 * p + 1], a, &b[2]);
            }
        }
        #pragma unroll
        for (int nt = 0; nt < 8; nt++) {
            int col = cg * 64 + nt * 8 + 2 * t4;
            float2 bp = *reinterpret_cast<const float2*>(&bproj[col]);
            #pragma unroll
            for (int r = 0; r < 2; r++) {
                int rloc = rh * 16 + gq + 8 * r;
                float2 sk = *reinterpret_cast<const float2*>(sSkip + rloc * 128 + col);
                float2 o2;
                o2.x = pacc[nt][2 * r] + bp.x + sk.x;
                o2.y = pacc[nt][2 * r + 1] + bp.y + sk.y;
                *reinterpret_cast<float2*>(out + ((size_t)l * 64 + rloc) * 128 + col) = o2;
            }
        }
    }
}

// ---------------- launch ----------------
extern "C" void kernel_launch(void* const* d_in, const int* in_sizes, int n_in,
                              void* d_out, int out_size) {
    const float* q     = (const float*)d_in[0];
    const float* k     = (const float*)d_in[1];
    const float* v     = (const float*)d_in[2];
    const float* skip  = (const float*)d_in[3];
    const float* freqs = (const float*)d_in[4];
    const float* gate  = (const float*)d_in[5];
    const float* lnqg  = (const float*)d_in[6];
    const float* lnqb  = (const float*)d_in[7];
    const float* lnkg  = (const float*)d_in[8];
    const float* lnkb  = (const float*)d_in[9];
    const float* lnvg  = (const float*)d_in[10];
    const float* lnvb  = (const float*)d_in[11];
    const float* wq    = (const float*)d_in[12];
    const float* bq    = (const float*)d_in[13];
    const float* wk    = (const float*)d_in[14];
    const float* bk    = (const float*)d_in[15];
    const float* wv    = (const float*)d_in[16];
    const float* bv    = (const float*)d_in[17];
    const float* wproj = (const float*)d_in[18];
    const float* bproj = (const float*)d_in[19];
    const float* als   = (const float*)d_in[20];
    float* out = (float*)d_out;

    static int smem_set = 0;
    if (!smem_set) {
        cudaFuncSetAttribute(fused_kernel, cudaFuncAttributeMaxDynamicSharedMemorySize, SMEM_BYTES);
        smem_set = 1;
    }

    prep_const_kernel<<<305, 256>>>(wq, wk, wv, wproj, freqs, gate, als);
    fused_kernel<<<LTOT, 256, SMEM_BYTES>>>(q, k, v, skip,
                                            lnqg, lnqb, lnkg, lnkb, lnvg, lnvb,
                                            bq, bk, bv, bproj, out);
}

// round 9
// speedup vs baseline: 1.3653x; 1.0299x over previous
#include <cuda_runtime.h>
#include <cuda_bf16.h>
#include <cuda_fp16.h>
#include <math.h>

// ---------------- problem constants ----------------
// B=1, N=6, X=Y=25 (L=625), W1=W2=8 (Qn=384), w1=w2=4 (Kn=96), D=128, M=4 heads, dh=32

#define LTOT 625
#define QN   384

// ---------------- device constants / scratch ----------------
__device__ __nv_bfloat16 g_wq[16384];
__device__ __nv_bfloat16 g_wk[16384];
__device__ __nv_bfloat16 g_wv[16384];
__device__ __nv_bfloat16 g_wp[16384];
__device__ __nv_bfloat16 g_tmp[(size_t)LTOT * 32 * 128];   // even-half O-mean spill
__device__ unsigned g_csb[QN * 32];                        // packed bf16x2 (cos, sin)
__device__ float g_scales[4];

// ---------------- helpers ----------------
__device__ __forceinline__ unsigned pk(float a, float b) {
    __nv_bfloat162 h = __floats2bfloat162_rn(a, b);
    return *reinterpret_cast<unsigned*>(&h);
}
__device__ __forceinline__ float2 bf2f(unsigned u) {
    __nv_bfloat162 h = *reinterpret_cast<__nv_bfloat162*>(&u);
    return __bfloat1622float2(h);
}
__device__ __forceinline__ __half2 u2h(unsigned u) {
    return *reinterpret_cast<__half2*>(&u);
}
__device__ __forceinline__ unsigned h2u(__half2 h) {
    return *reinterpret_cast<unsigned*>(&h);
}
// pack two f32 into f16x2: first arg -> HIGH half, second -> LOW half
__device__ __forceinline__ unsigned cvth2(float hi, float lo) {
    unsigned d;
    asm("cvt.rn.f16x2.f32 %0, %1, %2;\n" : "=r"(d) : "f"(hi), "f"(lo));
    return d;
}
__device__ __forceinline__ unsigned ex2h2(unsigned x) {
    unsigned y;
    asm("ex2.approx.f16x2 %0, %1;\n" : "=r"(y) : "r"(x));
    return y;
}
__device__ __forceinline__ unsigned ssa(const void* p) {
    return (unsigned)__cvta_generic_to_shared(p);
}
__device__ __forceinline__ void ldsm4(unsigned r[4], unsigned addr) {
    asm volatile("ldmatrix.sync.aligned.m8n8.x4.shared.b16 {%0,%1,%2,%3}, [%4];\n"
                 : "=r"(r[0]), "=r"(r[1]), "=r"(r[2]), "=r"(r[3]) : "r"(addr));
}
// bf16 mma
__device__ __forceinline__ void mma16816(float c[4], const unsigned a[4], const unsigned b[2]) {
    asm volatile(
        "mma.sync.aligned.m16n8k16.row.col.f32.bf16.bf16.f32 "
        "{%0,%1,%2,%3}, {%4,%5,%6,%7}, {%8,%9}, {%0,%1,%2,%3};\n"
        : "+f"(c[0]), "+f"(c[1]), "+f"(c[2]), "+f"(c[3])
        : "r"(a[0]), "r"(a[1]), "r"(a[2]), "r"(a[3]), "r"(b[0]), "r"(b[1]));
}
// fp16 mma (for P*V)
__device__ __forceinline__ void mma16816h(float c[4], const unsigned a[4], const unsigned b[2]) {
    asm volatile(
        "mma.sync.aligned.m16n8k16.row.col.f32.f16.f16.f32 "
        "{%0,%1,%2,%3}, {%4,%5,%6,%7}, {%8,%9}, {%0,%1,%2,%3};\n"
        : "+f"(c[0]), "+f"(c[1]), "+f"(c[2]), "+f"(c[3])
        : "r"(a[0]), "r"(a[1]), "r"(a[2]), "r"(a[3]), "r"(b[0]), "r"(b[1]));
}
__device__ __forceinline__ void cpa16(void* dst, const void* src) {
    asm volatile("cp.async.cg.shared.global [%0], [%1], 16;\n"
                 :: "r"(ssa(dst)), "l"(src));
}
__device__ __forceinline__ void cpa_commit() {
    asm volatile("cp.async.commit_group;\n");
}
template<int N> __device__ __forceinline__ void cpa_wait() {
    asm volatile("cp.async.wait_group %0;\n" :: "n"(N));
}

// ---------------- kernel 0: constants prep ----------------
__global__ __launch_bounds__(256) void prep_const_kernel(
    const float* __restrict__ wq, const float* __restrict__ wk,
    const float* __restrict__ wv, const float* __restrict__ wp,
    const float* __restrict__ freqs, const float* __restrict__ gate,
    const float* __restrict__ als)
{
    int idx = blockIdx.x * 256 + threadIdx.x;
    if (idx < 16384) {
        g_wq[idx] = __float2bfloat16(wq[idx]);
    } else if (idx < 32768) {
        g_wk[idx - 16384] = __float2bfloat16(wk[idx - 16384]);
    } else if (idx < 49152) {
        g_wv[idx - 32768] = __float2bfloat16(wv[idx - 32768]);
    } else if (idx < 65536) {
        g_wp[idx - 49152] = __float2bfloat16(wp[idx - 49152]);
    } else if (idx < 65536 + QN * 32) {
        int j = idx - 65536;
        float f = freqs[j];            // (400,32) row-major, t<384 prefix
        g_csb[j] = pk(cosf(f), sinf(f));
    } else if (idx < 65536 + QN * 32 + 4) {
        int m = idx - (65536 + QN * 32);
        float temp = als[m] - 0.5f * logf(32.0f);   // als + log(dh^-0.5)
        float ga = fminf(fmaxf(gate[m], 0.0f), 1.0f);
        g_scales[m] = temp * ga * 1.44269504f;      // fold log2(e): ex2 later
    }
}

// ---------------- smem layout (bf16 element offsets) ----------------
// sK   : 4*96*32 = 12288   K per head, SW64-XOR-swizzled (64B rows)
// sVt  : 4*32*104 = 13312  V^T[d][s] (fp16!) padded stride 104, per head
// sW   : 128*128 = 16384   weights, XOR-swizzled 16B units
// raw  : 8192 elems (16 KB) fp32 LN staging 32x128; Phase C: bf16 O 64x128 swizzled
// sCS  : 2048 elems (4 KB)  packed bf16x2 (cos,sin) for current 32-row chunk
// sX   : 32*136 = 4352     LN bf16 output staging
#define E_K   0
#define E_VT  12288
#define E_W   25600
#define E_RAW 41984
#define E_CS  50176
#define E_X   52224
#define SMEM_ELEMS 56576
#define SMEM_BYTES (SMEM_ELEMS * 2)   // 113152 -> 2 blocks/SM

__device__ __forceinline__ void stage_w(__nv_bfloat16* sW, const __nv_bfloat16* w, int tid) {
    #pragma unroll
    for (int u = tid; u < 2048; u += 256) {
        int row = u >> 4, cu = u & 15;
        cpa16(sW + row * 128 + ((cu ^ (row & 7)) << 3), w + u * 8);
    }
}
__device__ __forceinline__ void stage_chunk(float* raw, const float* x, int l,
                                            int t0, int sh, int msk, int tid) {
    #pragma unroll
    for (int j = 0; j < 4; j++) {
        int idx = tid + 256 * j;
        int row = idx >> 5, c4 = idx & 31;
        int t = t0 + row;
        int n = t >> sh, rem = t & msk;
        cpa16(raw + row * 128 + c4 * 4,
              x + ((size_t)(n * LTOT + l) * (msk + 1) + rem) * 128 + c4 * 4);
    }
}
__device__ __forceinline__ void stage_cs(unsigned* sCS, const unsigned* src, int tid) {
    cpa16(sCS + tid * 4, src + tid * 4);   // 256 threads x 16B = 4 KB
}

// ---------------- fused kernel: one block per l-tile, 2 blocks/SM ----------------
__global__ __launch_bounds__(256, 2) void fused_kernel(
    const float* __restrict__ q, const float* __restrict__ k,
    const float* __restrict__ v, const float* __restrict__ skip,
    const float* __restrict__ lnqg, const float* __restrict__ lnqb,
    const float* __restrict__ lnkg, const float* __restrict__ lnkb,
    const float* __restrict__ lnvg, const float* __restrict__ lnvb,
    const float* __restrict__ bq, const float* __restrict__ bk,
    const float* __restrict__ bv, const float* __restrict__ bproj,
    float* __restrict__ out)
{
    extern __shared__ __nv_bfloat16 sm[];
    __nv_bfloat16* sK  = sm + E_K;
    __nv_bfloat16* sVt = sm + E_VT;
    __nv_bfloat16* sW  = sm + E_W;
    float* raw = reinterpret_cast<float*>(sm + E_RAW);
    __nv_bfloat16* rawO = sm + E_RAW;
    unsigned* sCS = reinterpret_cast<unsigned*>(sm + E_CS);
    __nv_bfloat16* sX  = sm + E_X;
    __half* sVtH = reinterpret_cast<__half*>(sVt);

    int l = blockIdx.x;
    int tid = threadIdx.x;
    int wid = tid >> 5, lane = tid & 31, gq = lane >> 2, t4 = lane & 3;
    int mrow = (wid & 1) * 16;            // 16-row half within 32-row chunk
    int mh = wid >> 1;                    // head
    int lrow = tid >> 3, lsub = tid & 7;  // LN: 8 threads/row

    unsigned sWb = ssa(sW);
    unsigned abase = ssa(&sX[(mrow + (lane & 15)) * 136 + ((lane >> 4) << 3)]);

    // weight B-fragment lane constants (swizzled sW; 16B units, row stride 256 B)
    int o01 = mh * 32 + ((lane >> 4) << 3) + (lane & 7);
    unsigned wrow01 = sWb + o01 * 256;
    unsigned wrow23 = wrow01 + 4096;      // +16 output rows
    int wrx = o01 & 7;
    int wu0 = (lane >> 3) & 1;

    // K fragment bases (SW64-swizzled sK): second kk block = addr ^ 32
    char* sKb = reinterpret_cast<char*>(sK) + mh * 6144;
    unsigned kb0[6];
    {
        unsigned sKhb = ssa(sKb);
        int u0 = (lane >> 3) & 1;
        #pragma unroll
        for (int p = 0; p < 6; p++) {
            int tr = (2 * p + (lane >> 4)) * 8 + (lane & 7);
            kb0[p] = sKhb + tr * 64 + ((u0 ^ ((tr >> 1) & 3)) << 4);
        }
    }
    // V^T fragment bases (padded stride 104)
    __nv_bfloat16* sVh = sVt + mh * 32 * 104;
    unsigned vb[2];
    #pragma unroll
    for (int p = 0; p < 2; p++)
        vb[p] = ssa(&sVh[((2 * p + (lane >> 4)) * 8 + (lane & 7)) * 104 + (((lane >> 3) & 1) << 3)]);
    float sc = g_scales[mh];

    // initial: wk + first k chunk
    stage_w(sW, g_wk, tid);
    cpa_commit();
    stage_chunk(raw, k, l, 0, 4, 15, tid);
    cpa_commit();

    // =========================== Phase A: K (i=0..2) then V (i=3..5) prep ===========================
    for (int i = 0; i < 6; i++) {
        int isV = (i >= 3);
        cpa_wait<0>();
        __syncthreads();                        // chunk i arrived; prev epilogue reads of sCS done
        if (i < 3) { stage_cs(sCS, g_csb + i * 32 * 32, tid); cpa_commit(); }  // [A]
        if (i == 3) { stage_w(sW, g_wv, tid); cpa_commit(); }                  // [W]

        // LayerNorm 32 rows
        {
            const float* lng  = isV ? lnvg : lnkg;
            const float* lnb_ = isV ? lnvb : lnkb;
            const float* rp = raw + lrow * 128;
            float vv[16];
            #pragma unroll
            for (int i4 = 0; i4 < 4; i4++) {
                float4 f = *reinterpret_cast<const float4*>(rp + (lsub + 8 * i4) * 4);
                vv[4 * i4] = f.x; vv[4 * i4 + 1] = f.y; vv[4 * i4 + 2] = f.z; vv[4 * i4 + 3] = f.w;
            }
            float s = 0.f;
            #pragma unroll
            for (int i2 = 0; i2 < 16; i2++) s += vv[i2];
            #pragma unroll
            for (int o = 1; o < 8; o <<= 1) s += __shfl_xor_sync(0xffffffffu, s, o);
            float mu = s * (1.0f / 128.0f);
            float q2 = 0.f;
            #pragma unroll
            for (int i2 = 0; i2 < 16; i2++) { float d = vv[i2] - mu; q2 += d * d; }
            #pragma unroll
            for (int o = 1; o < 8; o <<= 1) q2 += __shfl_xor_sync(0xffffffffu, q2, o);
            float rs = rsqrtf(q2 * (1.0f / 128.0f) + 1e-5f);
            unsigned* xw = reinterpret_cast<unsigned*>(sX) + lrow * 68;
            #pragma unroll
            for (int i4 = 0; i4 < 4; i4++) {
                int c0 = lsub * 4 + i4 * 32;
                float a0 = (vv[4 * i4]     - mu) * rs * lng[c0]     + lnb_[c0];
                float a1 = (vv[4 * i4 + 1] - mu) * rs * lng[c0 + 1] + lnb_[c0 + 1];
                float a2 = (vv[4 * i4 + 2] - mu) * rs * lng[c0 + 2] + lnb_[c0 + 2];
                float a3 = (vv[4 * i4 + 3] - mu) * rs * lng[c0 + 3] + lnb_[c0 + 3];
                xw[2 * lsub + 16 * i4]     = pk(a0, a1);
                xw[2 * lsub + 16 * i4 + 1] = pk(a2, a3);
            }
        }
        __syncthreads();                        // raw free, sX ready
        if (i == 3) cpa_wait<0>();              // wv must be resident before GEMM
        // prefetch next chunk into raw                                        // [B]
        if (i < 2)       stage_chunk(raw, k, l, (i + 1) * 32, 4, 15, tid);
        else if (i < 5)  stage_chunk(raw, v, l, (i - 2) * 32, 4, 15, tid);
        else             stage_chunk(raw, q, l, 0, 6, 63, tid);
        cpa_commit();

        // GEMM: 32 rows x 128 cols
        float acc[4][4] = {};
        #pragma unroll
        for (int kk = 0; kk < 128; kk += 16) {
            unsigned uoff = ((((kk >> 3) + wu0) ^ wrx) << 4);
            unsigned a[4], b01[4], b23[4];
            ldsm4(a, abase + kk * 2);
            ldsm4(b01, wrow01 + uoff);
            ldsm4(b23, wrow23 + uoff);
            mma16816(acc[0], a, &b01[0]);
            mma16816(acc[1], a, &b01[2]);
            mma16816(acc[2], a, &b23[0]);
            mma16816(acc[3], a, &b23[2]);
        }
        cpa_wait<1>();                          // cs chunk arrived (no-op for V iters)

        if (!isV) {
            // K: +bias -> RoPE(bf16 trig from sCS) -> sK (SW64 swizzled)
            #pragma unroll
            for (int r = 0; r < 2; r++) {
                int lt = mrow + gq + 8 * r;
                int t = i * 32 + lt;
                #pragma unroll
                for (int ntl = 0; ntl < 2; ntl++) {
                    int jlo = ntl * 8 + 2 * t4;
                    int jhi = jlo + 16;
                    float2 blo = *reinterpret_cast<const float2*>(&bk[mh * 32 + jlo]);
                    float2 bhi = *reinterpret_cast<const float2*>(&bk[mh * 32 + jhi]);
                    float plo0 = acc[ntl][2 * r] + blo.x;
                    float plo1 = acc[ntl][2 * r + 1] + blo.y;
                    float phi0 = acc[ntl + 2][2 * r] + bhi.x;
                    float phi1 = acc[ntl + 2][2 * r + 1] + bhi.y;
                    uint2 ulo = *reinterpret_cast<const uint2*>(&sCS[lt * 32 + jlo]);
                    uint2 uhi = *reinterpret_cast<const uint2*>(&sCS[lt * 32 + jhi]);
                    float2 cs0 = bf2f(ulo.x), cs1 = bf2f(ulo.y);
                    float2 cs2 = bf2f(uhi.x), cs3 = bf2f(uhi.y);
                    unsigned off0 = t * 64 + jlo * 2;
                    unsigned off1 = t * 64 + jhi * 2;
                    *reinterpret_cast<unsigned*>(sKb + (off0 ^ ((off0 >> 3) & 0x30))) =
                        pk(plo0 * cs0.x - phi0 * cs0.y, plo1 * cs1.x - phi1 * cs1.y);
                    *reinterpret_cast<unsigned*>(sKb + (off1 ^ ((off1 >> 3) & 0x30))) =
                        pk(phi0 * cs2.x + plo0 * cs2.y, phi1 * cs3.x + plo1 * cs3.y);
                }
            }
        } else {
            // V: +bias -> transpose into sVt as FP16 (for fp16 PV mma)
            #pragma unroll
            for (int r = 0; r < 2; r++) {
                int t = (i - 3) * 32 + mrow + gq + 8 * r;
                #pragma unroll
                for (int ntl = 0; ntl < 2; ntl++) {
                    int jlo = ntl * 8 + 2 * t4;
                    int jhi = jlo + 16;
                    float2 blo = *reinterpret_cast<const float2*>(&bv[mh * 32 + jlo]);
                    float2 bhi = *reinterpret_cast<const float2*>(&bv[mh * 32 + jhi]);
                    sVtH[(mh * 32 + jlo) * 104 + t]     = __float2half(acc[ntl][2 * r] + blo.x);
                    sVtH[(mh * 32 + jlo + 1) * 104 + t] = __float2half(acc[ntl][2 * r + 1] + blo.y);
                    sVtH[(mh * 32 + jhi) * 104 + t]     = __float2half(acc[ntl + 2][2 * r] + bhi.x);
                    sVtH[(mh * 32 + jhi + 1) * 104 + t] = __float2half(acc[ntl + 2][2 * r + 1] + bhi.y);
                }
            }
        }
    }

    // =========================== Phase B: Q prep + attention + mean ===========================
    float moacc[4][4] = {};

    for (int j = 0; j < 12; j++) {
        int qc = (j < 6) ? 2 * j : 2 * j - 11;   // even uv-half first, then odd
        cpa_wait<0>();
        __syncthreads();                          // raw_j arrived; prev sCS reads done
        stage_cs(sCS, g_csb + qc * 32 * 32, tid); cpa_commit();       // [A]
        if (j == 0) { stage_w(sW, g_wq, tid); cpa_commit(); }         // [W]

        // LayerNorm (q)
        {
            const float* rp = raw + lrow * 128;
            float vv[16];
            #pragma unroll
            for (int i4 = 0; i4 < 4; i4++) {
                float4 f = *reinterpret_cast<const float4*>(rp + (lsub + 8 * i4) * 4);
                vv[4 * i4] = f.x; vv[4 * i4 + 1] = f.y; vv[4 * i4 + 2] = f.z; vv[4 * i4 + 3] = f.w;
            }
            float s = 0.f;
            #pragma unroll
            for (int i2 = 0; i2 < 16; i2++) s += vv[i2];
            #pragma unroll
            for (int o = 1; o < 8; o <<= 1) s += __shfl_xor_sync(0xffffffffu, s, o);
            float mu = s * (1.0f / 128.0f);
            float q2 = 0.f;
            #pragma unroll
            for (int i2 = 0; i2 < 16; i2++) { float d = vv[i2] - mu; q2 += d * d; }
            #pragma unroll
            for (int o = 1; o < 8; o <<= 1) q2 += __shfl_xor_sync(0xffffffffu, q2, o);
            float rs = rsqrtf(q2 * (1.0f / 128.0f) + 1e-5f);
            unsigned* xw = reinterpret_cast<unsigned*>(sX) + lrow * 68;
            #pragma unroll
            for (int i4 = 0; i4 < 4; i4++) {
                int c0 = lsub * 4 + i4 * 32;
                float a0 = (vv[4 * i4]     - mu) * rs * lnqg[c0]     + lnqb[c0];
                float a1 = (vv[4 * i4 + 1] - mu) * rs * lnqg[c0 + 1] + lnqb[c0 + 1];
                float a2 = (vv[4 * i4 + 2] - mu) * rs * lnqg[c0 + 2] + lnqb[c0 + 2];
                float a3 = (vv[4 * i4 + 3] - mu) * rs * lnqg[c0 + 3] + lnqb[c0 + 3];
                xw[2 * lsub + 16 * i4]     = pk(a0, a1);
                xw[2 * lsub + 16 * i4 + 1] = pk(a2, a3);
            }
        }
        __syncthreads();
        if (j == 0) cpa_wait<0>();              // wq resident before GEMM
        if (j < 11) {
            int j2 = j + 1;
            int qc2 = (j2 < 6) ? 2 * j2 : 2 * j2 - 11;
            stage_chunk(raw, q, l, qc2 * 32, 6, 63, tid);             // [B]
            cpa_commit();
        }

        // q GEMM
        float acc[4][4] = {};
        #pragma unroll
        for (int kk = 0; kk < 128; kk += 16) {
            unsigned uoff = ((((kk >> 3) + wu0) ^ wrx) << 4);
            unsigned a[4], b01[4], b23[4];
            ldsm4(a, abase + kk * 2);
            ldsm4(b01, wrow01 + uoff);
            ldsm4(b23, wrow23 + uoff);
            mma16816(acc[0], a, &b01[0]);
            mma16816(acc[1], a, &b01[2]);
            mma16816(acc[2], a, &b23[0]);
            mma16816(acc[3], a, &b23[2]);
        }
        if (j < 11) cpa_wait<1>(); else cpa_wait<0>();   // cs arrived

        // epilogue: +bias -> RoPE(bf16 trig) -> *scale(log2e folded) -> A fragments
        unsigned aq0[4], aq1[4];
        {
            float F[4][4];
            #pragma unroll
            for (int r = 0; r < 2; r++) {
                int lt = mrow + gq + 8 * r;
                #pragma unroll
                for (int ntl = 0; ntl < 2; ntl++) {
                    int jlo = ntl * 8 + 2 * t4;
                    int jhi = jlo + 16;
                    float2 blo = *reinterpret_cast<const float2*>(&bq[mh * 32 + jlo]);
                    float2 bhi = *reinterpret_cast<const float2*>(&bq[mh * 32 + jhi]);
                    float plo0 = acc[ntl][2 * r] + blo.x;
                    float plo1 = acc[ntl][2 * r + 1] + blo.y;
                    float phi0 = acc[ntl + 2][2 * r] + bhi.x;
                    float phi1 = acc[ntl + 2][2 * r + 1] + bhi.y;
                    uint2 ulo = *reinterpret_cast<const uint2*>(&sCS[lt * 32 + jlo]);
                    uint2 uhi = *reinterpret_cast<const uint2*>(&sCS[lt * 32 + jhi]);
                    float2 cs0 = bf2f(ulo.x), cs1 = bf2f(ulo.y);
                    float2 cs2 = bf2f(uhi.x), cs3 = bf2f(uhi.y);
                    F[ntl][2 * r]         = (plo0 * cs0.x - phi0 * cs0.y) * sc;
                    F[ntl][2 * r + 1]     = (plo1 * cs1.x - phi1 * cs1.y) * sc;
                    F[ntl + 2][2 * r]     = (phi0 * cs2.x + plo0 * cs2.y) * sc;
                    F[ntl + 2][2 * r + 1] = (phi1 * cs3.x + plo1 * cs3.y) * sc;
                }
            }
            aq0[0] = pk(F[0][0], F[0][1]); aq0[1] = pk(F[0][2], F[0][3]);
            aq0[2] = pk(F[1][0], F[1][1]); aq0[3] = pk(F[1][2], F[1][3]);
            aq1[0] = pk(F[2][0], F[2][1]); aq1[1] = pk(F[2][2], F[2][3]);
            aq1[2] = pk(F[3][0], F[3][1]); aq1[3] = pk(F[3][2], F[3][3]);
        }

        // S = Q K^T over 96 keys (SW64-swizzled K; kk block 1 = addr ^ 32)
        float sacc[12][4] = {};
        #pragma unroll
        for (int p = 0; p < 6; p++) {
            unsigned b[4];
            ldsm4(b, kb0[p]);
            mma16816(sacc[2 * p], aq0, &b[0]);
            mma16816(sacc[2 * p + 1], aq0, &b[2]);
        }
        #pragma unroll
        for (int p = 0; p < 6; p++) {
            unsigned b[4];
            ldsm4(b, kb0[p] ^ 32u);
            mma16816(sacc[2 * p], aq1, &b[0]);
            mma16816(sacc[2 * p + 1], aq1, &b[2]);
        }

        // fp16x2 softmax: exp2 packed; sums via HADD2 tree; normalize packed.
        // hx[nt] = exp row gq (cols pair), hy[nt] = exp row gq+8
        unsigned hx[12], hy[12];
        #pragma unroll
        for (int nt = 0; nt < 12; nt++) {
            hx[nt] = ex2h2(cvth2(sacc[nt][1], sacc[nt][0]));
            hy[nt] = ex2h2(cvth2(sacc[nt][3], sacc[nt][2]));
        }
        __half2 s2x = u2h(hx[0]), s2y = u2h(hy[0]);
        #pragma unroll
        for (int nt = 1; nt < 12; nt++) {
            s2x = __hadd2(s2x, u2h(hx[nt]));
            s2y = __hadd2(s2y, u2h(hy[nt]));
        }
        float sm0 = __low2float(s2x) + __high2float(s2x);
        float sm1 = __low2float(s2y) + __high2float(s2y);
        sm0 += __shfl_xor_sync(0xffffffffu, sm0, 1);
        sm0 += __shfl_xor_sync(0xffffffffu, sm0, 2);
        sm1 += __shfl_xor_sync(0xffffffffu, sm1, 1);
        sm1 += __shfl_xor_sync(0xffffffffu, sm1, 2);
        float r0i = __fdividef(0.16666667f, sm0);
        float r1i = __fdividef(0.16666667f, sm1);
        unsigned rr0 = cvth2(r0i, r0i);
        unsigned rr1 = cvth2(r1i, r1i);
        #pragma unroll
        for (int nt = 0; nt < 12; nt++) {
            hx[nt] = h2u(__hmul2(u2h(hx[nt]), u2h(rr0)));
            hy[nt] = h2u(__hmul2(u2h(hy[nt]), u2h(rr1)));
        }

        // O += (P/6) V via fp16 mma — hx/hy ARE the A fragments
        #pragma unroll
        for (int c6 = 0; c6 < 6; c6++) {
            unsigned a[4];
            a[0] = hx[2 * c6];
            a[1] = hy[2 * c6];
            a[2] = hx[2 * c6 + 1];
            a[3] = hy[2 * c6 + 1];
            #pragma unroll
            for (int p = 0; p < 2; p++) {
                unsigned b[4];
                ldsm4(b, vb[p] + c6 * 32);
                mma16816h(moacc[2 * p], a, &b[0]);
                mma16816h(moacc[2 * p + 1], a, &b[2]);
            }
        }

        if (j == 5) {
            // flush even uv-half mean to global scratch; reset accumulator
            #pragma unroll
            for (int nt = 0; nt < 4; nt++) {
                int col = mh * 32 + nt * 8 + 2 * t4;
                #pragma unroll
                for (int r = 0; r < 2; r++) {
                    int uv = mrow + gq + 8 * r;
                    *reinterpret_cast<unsigned*>(g_tmp + (size_t)l * 4096 + uv * 128 + col) =
                        pk(moacc[nt][2 * r], moacc[nt][2 * r + 1]);
                }
            }
            #pragma unroll
            for (int nt = 0; nt < 4; nt++)
                #pragma unroll
                for (int e = 0; e < 4; e++) moacc[nt][e] = 0.f;
        }
    }

    // =========================== Phase C: mean -> proj -> +skip -> out ===========================
    __syncthreads();   // all attention reads of sK/sVt/sW/raw done

    // odd uv-half: registers -> rawO rows 32..63 (swizzled bf16 64x128)
    #pragma unroll
    for (int nt = 0; nt < 4; nt++) {
        int col = mh * 32 + nt * 8 + 2 * t4;
        int cu = col >> 3;
        #pragma unroll
        for (int r = 0; r < 2; r++) {
            int row = 32 + mrow + gq + 8 * r;
            *reinterpret_cast<unsigned*>(&rawO[row * 128 + ((cu ^ (row & 7)) << 3) + (col & 7)]) =
                pk(moacc[nt][2 * r], moacc[nt][2 * r + 1]);
        }
    }
    // stage wp, even uv-half (g_tmp), skip
    stage_w(sW, g_wp, tid);
    #pragma unroll
    for (int u = tid; u < 512; u += 256) {
        int row = u >> 4, cu = u & 15;
        cpa16(&rawO[row * 128 + ((cu ^ (row & 7)) << 3)],
              g_tmp + (size_t)l * 4096 + row * 128 + cu * 8);
    }
    float* sSkip = reinterpret_cast<float*>(sm + E_K);   // 32 KB inside dead sK/sVt region
    #pragma unroll
    for (int u = tid; u < 2048; u += 256)
        cpa16(sSkip + u * 4, skip + (size_t)l * 8192 + u * 4);
    cpa_commit();
    cpa_wait<0>();
    __syncthreads();

    // proj GEMM: 64 rows x 128 cols; warp = (rh = wid&3 rowtile, cg = wid>>2 colgroup of 64)
    {
        int rh = wid & 3, cg = wid >> 2;
        int prowA = rh * 16 + (lane & 15);
        unsigned paRow = ssa(rawO) + prowA * 256;
        int parx = prowA & 7, pau0 = lane >> 4;
        int op = cg * 64 + ((lane >> 4) << 3) + (lane & 7);
        unsigned pw0 = sWb + op * 256;
        int prx = op & 7;
        float pacc[8][4] = {};
        #pragma unroll
        for (int kk = 0; kk < 128; kk += 16) {
            unsigned a[4];
            ldsm4(a, paRow + ((((kk >> 3) + pau0) ^ parx) << 4));
            unsigned uoff = ((((kk >> 3) + wu0) ^ prx) << 4);
            #pragma unroll
            for (int p = 0; p < 4; p++) {
                unsigned b[4];
                ldsm4(b, pw0 + p * 4096 + uoff);
                mma16816(pacc[2 * p], a, &b[0]);
                mma16816(pacc[2 * p + 1], a, &b[2]);
            }
        }
        #pragma unroll
        for (int nt = 0; nt < 8; nt++) {
            int col = cg * 64 + nt * 8 + 2 * t4;
            float2 bp = *reinterpret_cast<const float2*>(&bproj[col]);
            #pragma unroll
            for (int r = 0; r < 2; r++) {
                int rloc = rh * 16 + gq + 8 * r;
                float2 sk = *reinterpret_cast<const float2*>(sSkip + rloc * 128 + col);
                float2 o2;
                o2.x = pacc[nt][2 * r] + bp.x + sk.x;
                o2.y = pacc[nt][2 * r + 1] + bp.y + sk.y;
                *reinterpret_cast<float2*>(out + ((size_t)l * 64 + rloc) * 128 + col) = o2;
            }
        }
    }
}

// ---------------- launch ----------------
extern "C" void kernel_launch(void* const* d_in, const int* in_sizes, int n_in,
                              void* d_out, int out_size) {
    const float* q     = (const float*)d_in[0];
    const float* k     = (const float*)d_in[1];
    const float* v     = (const float*)d_in[2];
    const float* skip  = (const float*)d_in[3];
    const float* freqs = (const float*)d_in[4];
    const float* gate  = (const float*)d_in[5];
    const float* lnqg  = (const float*)d_in[6];
    const float* lnqb  = (const float*)d_in[7];
    const float* lnkg  = (const float*)d_in[8];
    const float* lnkb  = (const float*)d_in[9];
    const float* lnvg  = (const float*)d_in[10];
    const float* lnvb  = (const float*)d_in[11];
    const float* wq    = (const float*)d_in[12];
    const float* bq    = (const float*)d_in[13];
    const float* wk    = (const float*)d_in[14];
    const float* bk    = (const float*)d_in[15];
    const float* wv    = (const float*)d_in[16];
    const float* bv    = (const float*)d_in[17];
    const float* wproj = (const float*)d_in[18];
    const float* bproj = (const float*)d_in[19];
    const float* als   = (const float*)d_in[20];
    float* out = (float*)d_out;

    static int smem_set = 0;
    if (!smem_set) {
        cudaFuncSetAttribute(fused_kernel, cudaFuncAttributeMaxDynamicSharedMemorySize, SMEM_BYTES);
        smem_set = 1;
    }

    prep_const_kernel<<<305, 256>>>(wq, wk, wv, wproj, freqs, gate, als);
    fused_kernel<<<LTOT, 256, SMEM_BYTES>>>(q, k, v, skip,
                                            lnqg, lnqb, lnkg, lnkb, lnvg, lnvb,
                                            bq, bk, bv, bproj, out);
}